// round 8
// baseline (speedup 1.0000x reference)
#include <cuda_runtime.h>
#include <cuda_bf16.h>
#include <stdint.h>

#define N_NODES 100000
#define N_EDGES 1600000
#define NUM_RELS 8
#define H_DIM 64
#define K_TOT 512
#define NSEG (N_NODES * NUM_RELS)          // 800000
#define NLDA 72                            // bf16 elems; 144B row stride
#define ALDA 68                            // Aacc fp32 leading dim
#define NB_SM 782
#define NB_PREPW 256
#define NB_HIST 6250
#define SCAN_NB 782

// ---------------- scratch ----------------
__device__ float g_x[(size_t)N_NODES * H_DIM];
__device__ float g_h[(size_t)N_NODES * H_DIM];
__device__ int   g_cnt[SCAN_NB * 1024];     // zero-init; re-zeroed by scan each run
__device__ int   g_rowptr[NSEG + 1];
__device__ int   g_wp[NSEG];
__device__ unsigned long long g_flags[SCAN_NB];  // zero-init; re-zeroed by scatter
__device__ int2  g_emeta[N_EDGES];          // {src, norm-bits}, CSR order
__device__ __nv_bfloat16 g_Wth[2 * H_DIM * K_TOT];   // [layer][o*512 + r*64+k]
__device__ __nv_bfloat16 g_Wtl[2 * H_DIM * K_TOT];

// ---------------- helpers ----------------
__device__ __forceinline__ void mma16816(float* c, const uint32_t* a, const uint32_t* b) {
    asm volatile(
        "mma.sync.aligned.m16n8k16.row.col.f32.bf16.bf16.f32 "
        "{%0,%1,%2,%3}, {%4,%5,%6,%7}, {%8,%9}, {%0,%1,%2,%3};\n"
        : "+f"(c[0]), "+f"(c[1]), "+f"(c[2]), "+f"(c[3])
        : "r"(a[0]), "r"(a[1]), "r"(a[2]), "r"(a[3]), "r"(b[0]), "r"(b[1]));
}

__device__ __forceinline__ void ldsm4(uint32_t* r, uint32_t addr) {
    asm volatile("ldmatrix.sync.aligned.m8n8.x4.shared.b16 {%0,%1,%2,%3}, [%4];"
        : "=r"(r[0]), "=r"(r[1]), "=r"(r[2]), "=r"(r[3]) : "r"(addr));
}

__device__ __forceinline__ void split_bf16(float v, __nv_bfloat16& hi, __nv_bfloat16& lo) {
    hi = __float2bfloat16(v);
    lo = __float2bfloat16(v - __bfloat162float(hi));
}

// ---------------- size matcher body (256 threads/block) ----------------
__device__ void sm_body(int bid, const int* __restrict__ feat, const float* __restrict__ emb,
                        const float* __restrict__ smw, const float* __restrict__ smb,
                        char* smraw) {
    __nv_bfloat16* Ahi = (__nv_bfloat16*)smraw;
    __nv_bfloat16* Alo = Ahi + 128 * NLDA;
    __nv_bfloat16* Bhi = Alo + 128 * NLDA;
    __nv_bfloat16* Blo = Bhi + 64 * NLDA;
    int* sfeat = (int*)(Blo + 64 * NLDA);

    int tid = threadIdx.x;
    int rb = bid * 128;

    for (int idx = tid; idx < 128 * 8; idx += 256) {
        int r = idx >> 3, j = idx & 7;
        sfeat[idx] = (rb + r < N_NODES) ? feat[(size_t)(rb + r) * 8 + j] : 0;
    }

    int lane = tid & 31, warp = tid >> 5;
    int wr = (warp >> 2) * 64;
    int wc = (warp & 3) * 16;
    int g = lane >> 2, t = lane & 3;

    float C[8][4];
    #pragma unroll
    for (int i = 0; i < 8; i++)
        #pragma unroll
        for (int j = 0; j < 4; j++) C[i][j] = 0.f;

    for (int kc = 0; kc < 4; kc++) {
        __syncthreads();
        for (int idx = tid; idx < 128 * 64; idx += 256) {
            int r = idx >> 6, k = idx & 63;
            float v = 0.f;
            if (rb + r < N_NODES) {
                int fid = sfeat[r * 8 + kc * 2 + (k >> 5)];
                v = emb[(size_t)fid * 32 + (k & 31)];
            }
            __nv_bfloat16 h, l; split_bf16(v, h, l);
            Ahi[r * NLDA + k] = h; Alo[r * NLDA + k] = l;
        }
        for (int idx = tid; idx < 64 * 64; idx += 256) {
            int n = idx >> 6, k = idx & 63;
            float v = smw[n * 256 + kc * 64 + k];
            __nv_bfloat16 h, l; split_bf16(v, h, l);
            Bhi[n * NLDA + k] = h; Blo[n * NLDA + k] = l;
        }
        __syncthreads();

        #pragma unroll
        for (int ks = 0; ks < 4; ks++) {
            int k0 = ks * 16;
            #pragma unroll
            for (int p = 0; p < 3; p++) {
                const __nv_bfloat16* As = (p == 1) ? Alo : Ahi;
                const __nv_bfloat16* Bs = (p == 2) ? Blo : Bhi;
                uint32_t a[4][4], b[2][2];
                #pragma unroll
                for (int mt = 0; mt < 4; mt++) {
                    int r0 = wr + mt * 16;
                    a[mt][0] = *(const uint32_t*)(As + (r0 + g) * NLDA + k0 + 2 * t);
                    a[mt][1] = *(const uint32_t*)(As + (r0 + g + 8) * NLDA + k0 + 2 * t);
                    a[mt][2] = *(const uint32_t*)(As + (r0 + g) * NLDA + k0 + 8 + 2 * t);
                    a[mt][3] = *(const uint32_t*)(As + (r0 + g + 8) * NLDA + k0 + 8 + 2 * t);
                }
                #pragma unroll
                for (int nt = 0; nt < 2; nt++) {
                    int c0 = wc + nt * 8 + g;
                    b[nt][0] = *(const uint32_t*)(Bs + c0 * NLDA + k0 + 2 * t);
                    b[nt][1] = *(const uint32_t*)(Bs + c0 * NLDA + k0 + 8 + 2 * t);
                }
                #pragma unroll
                for (int mt = 0; mt < 4; mt++)
                    #pragma unroll
                    for (int nt = 0; nt < 2; nt++)
                        mma16816(C[mt * 2 + nt], a[mt], b[nt]);
            }
        }
    }

    #pragma unroll
    for (int mt = 0; mt < 4; mt++) {
        int r0 = rb + wr + mt * 16 + g;
        int r1 = r0 + 8;
        #pragma unroll
        for (int nt = 0; nt < 2; nt++) {
            int gc = wc + nt * 8 + 2 * t;
            float b0 = smb[gc], b1 = smb[gc + 1];
            if (r0 < N_NODES)
                *(float2*)(g_x + (size_t)r0 * 64 + gc) =
                    make_float2(C[mt * 2 + nt][0] + b0, C[mt * 2 + nt][1] + b1);
            if (r1 < N_NODES)
                *(float2*)(g_x + (size_t)r1 * 64 + gc) =
                    make_float2(C[mt * 2 + nt][2] + b0, C[mt * 2 + nt][3] + b1);
        }
    }
}

// ---------------- front kernel: sm + prepw + hist ----------------
__global__ void k_front(const int* __restrict__ feat, const float* __restrict__ emb,
                        const float* __restrict__ smw, const float* __restrict__ smb,
                        const float* __restrict__ V1, const float* __restrict__ c1,
                        const float* __restrict__ V2, const float* __restrict__ c2,
                        const int* __restrict__ dst, const int* __restrict__ etype) {
    extern __shared__ char smraw[];
    int bid = blockIdx.x;
    if (bid < NB_SM) {
        sm_body(bid, feat, emb, smw, smb, smraw);
    } else if (bid < NB_SM + NB_PREPW) {
        int t = (bid - NB_SM) * 256 + threadIdx.x;
        int sel = t >= H_DIM * K_TOT;
        int u = t & (H_DIM * K_TOT - 1);
        int o = u >> 9;
        int c = u & 511;
        int r = c >> 6, k = c & 63;
        const float* V = sel ? V2 : V1;
        const float* cp = sel ? c2 : c1;
        float s = 0.f;
        #pragma unroll
        for (int b = 0; b < 8; b++)
            s += cp[r * 8 + b] * V[(b * 64 + k) * 64 + o];
        __nv_bfloat16 hi = __float2bfloat16(s);
        __nv_bfloat16 lo = __float2bfloat16(s - __bfloat162float(hi));
        g_Wth[t] = hi;
        g_Wtl[t] = lo;
    } else {
        int e = (bid - NB_SM - NB_PREPW) * 256 + threadIdx.x;
        if (e < N_EDGES)
            atomicAdd(&g_cnt[etype[e] * N_NODES + dst[e]], 1);
    }
}

// ---------------- single-kernel scan (decoupled lookback) ----------------
__global__ __launch_bounds__(1024) void k_scan() {
    __shared__ int wsum[32];
    __shared__ int s_excl;
    int tid = threadIdx.x, b = blockIdx.x;
    int i = b * 1024 + tid;
    int v = (i < NSEG) ? g_cnt[i] : 0;
    int lane = tid & 31, wid = tid >> 5;
    int s = v;
    #pragma unroll
    for (int d = 1; d < 32; d <<= 1) {
        int t = __shfl_up_sync(0xFFFFFFFFu, s, d);
        if (lane >= d) s += t;
    }
    if (lane == 31) wsum[wid] = s;
    __syncthreads();
    if (wid == 0) {
        int ws = wsum[lane];
        #pragma unroll
        for (int d = 1; d < 32; d <<= 1) {
            int t = __shfl_up_sync(0xFFFFFFFFu, ws, d);
            if (lane >= d) ws += t;
        }
        wsum[lane] = ws;
    }
    __syncthreads();
    int incl = s + ((wid > 0) ? wsum[wid - 1] : 0);
    int total = wsum[31];

    if (tid == 0) {
        unsigned long long f =
            ((unsigned long long)((b == 0) ? 2u : 1u) << 32) | (unsigned)total;
        atomicExch(&g_flags[b], f);
        if (b == 0) s_excl = 0;
    }
    if (b > 0 && wid == 0) {
        int running = 0;
        int p = b - 1;
        while (true) {
            int idx = p - lane;
            unsigned long long f = (idx >= 0) ? atomicOr(&g_flags[idx], 0ULL)
                                              : (2ULL << 32);
            unsigned st = (unsigned)(f >> 32);
            if (__ballot_sync(0xFFFFFFFFu, st == 0)) continue;
            unsigned b2 = __ballot_sync(0xFFFFFFFFu, st == 2);
            int val = (int)(unsigned)f;
            if (b2) {
                int k = __ffs(b2) - 1;
                int contrib = (lane <= k) ? val : 0;
                #pragma unroll
                for (int off = 16; off > 0; off >>= 1)
                    contrib += __shfl_xor_sync(0xFFFFFFFFu, contrib, off);
                running += contrib;
                break;
            } else {
                int contrib = val;
                #pragma unroll
                for (int off = 16; off > 0; off >>= 1)
                    contrib += __shfl_xor_sync(0xFFFFFFFFu, contrib, off);
                running += contrib;
                p -= 32;
            }
        }
        if (lane == 0) {
            s_excl = running;
            unsigned long long f = (2ULL << 32) | (unsigned)(running + total);
            atomicExch(&g_flags[b], f);
        }
    }
    __syncthreads();
    int rp = s_excl + incl - v;
    if (i < NSEG) {
        g_rowptr[i] = rp;
        g_wp[i] = rp;
        g_cnt[i] = 0;
    }
    if (i == NSEG - 1) g_rowptr[NSEG] = rp + v;
}

// ---------------- scatter (also re-zeroes g_flags) ----------------
__global__ void k_scatter(const int* __restrict__ src, const int* __restrict__ dst,
                          const int* __restrict__ etype, const float* __restrict__ norm) {
    int gid = blockIdx.x * blockDim.x + threadIdx.x;
    if (gid < SCAN_NB) g_flags[gid] = 0ULL;
    if (gid >= N_EDGES) return;
    int seg = etype[gid] * N_NODES + dst[gid];
    int p = atomicAdd(&g_wp[seg], 1);
    g_emeta[p] = make_int2(src[gid], __float_as_int(norm[gid]));
}

// ---------------- fused layer v4: paired half-warp gathers + dual-bank Aacc --------
__global__ __launch_bounds__(512, 2)
void k_fused(int phase, const float* __restrict__ bias, float* __restrict__ dout) {
    const float* __restrict__ X = phase ? g_h : g_x;
    float* __restrict__ OP = phase ? dout : g_h;
    const __nv_bfloat16* __restrict__ Wh = g_Wth + phase * H_DIM * K_TOT;
    const __nv_bfloat16* __restrict__ Wl = g_Wtl + phase * H_DIM * K_TOT;

    extern __shared__ char smraw[];
    __nv_bfloat16* Ahi = (__nv_bfloat16*)smraw;         // 128*72 (18432 B)
    __nv_bfloat16* Alo = Ahi + 128 * NLDA;              // 18432 B
    float* Aacc = (float*)(Alo + 128 * NLDA);           // 256 rows * 68 fp32 (69632 B)

    int tid = threadIdx.x;
    int rb = blockIdx.x * 128;
    int lane = tid & 31, warp = tid >> 5;
    int c = lane * 2;
    int half = lane >> 4;                // which edge of the pair this lane serves
    int col4 = (lane & 15) * 4;          // 4 fp32 columns per lane

    int wr = (warp >> 2) * 32;
    int wc = (warp & 3) * 16;
    int g = lane >> 2, t = lane & 3;

    // ldmatrix per-lane A addresses (same mapping as validated in v3)
    int rowA = (lane & 7) + ((lane >> 3) & 1) * 8;
    int colA = ((lane >> 4) & 1) * 8;
    uint32_t aHiAddr = (uint32_t)__cvta_generic_to_shared(Ahi) + (wr + rowA) * (NLDA * 2) + colA * 2;
    uint32_t aLoAddr = (uint32_t)__cvta_generic_to_shared(Alo) + (wr + rowA) * (NLDA * 2) + colA * 2;

    // direct-global B fragment base offsets (match ldmatrix layout; see v3 derivation)
    const __nv_bfloat16* Wh0 = Wh + (wc + g) * K_TOT + 2 * t;
    const __nv_bfloat16* Wh8 = Wh + (wc + 8 + g) * K_TOT + 2 * t;
    const __nv_bfloat16* Wl0 = Wl + (wc + g) * K_TOT + 2 * t;
    const __nv_bfloat16* Wl8 = Wl + (wc + 8 + g) * K_TOT + 2 * t;

    float* AaccW = Aacc + (warp * 16) * ALDA;   // this warp's 16-row slab (2 banks)
    float* abase = AaccW + (half * 8) * ALDA + col4;

    float C[4][4];
    #pragma unroll
    for (int i = 0; i < 4; i++)
        #pragma unroll
        for (int j = 0; j < 4; j++) C[i][j] = 0.f;

    for (int r = 0; r < NUM_RELS; r++) {
        // ===== zero own Aacc bank rows =====
        #pragma unroll
        for (int i = 0; i < 8; i++)
            *(float4*)(abase + i * ALDA) = make_float4(0.f, 0.f, 0.f, 0.f);

        // ===== rowptr bounds for this warp's 8 rows =====
        int segbase = r * N_NODES + rb + warp * 8;
        int clampmax = r * N_NODES + N_NODES;
        int bp = 0;
        if (lane <= 8) bp = g_rowptr[min(segbase + lane, clampmax)];
        int wbeg = __shfl_sync(0xFFFFFFFFu, bp, 0);
        int wend = __shfl_sync(0xFFFFFFFFu, bp, 8);
        int b1 = __shfl_sync(0xFFFFFFFFu, bp, 1);
        int b2 = __shfl_sync(0xFFFFFFFFu, bp, 2);
        int b3 = __shfl_sync(0xFFFFFFFFu, bp, 3);
        int b4 = __shfl_sync(0xFFFFFFFFu, bp, 4);
        int b5 = __shfl_sync(0xFFFFFFFFu, bp, 5);
        int b6 = __shfl_sync(0xFFFFFFFFu, bp, 6);
        int b7 = __shfl_sync(0xFFFFFFFFu, bp, 7);
        int cnt = wend - wbeg;

        // ===== aggregation: 2 edges per warp-instruction =====
        for (int jb = 0; jb < cnt; jb += 32) {
            int ge = wbeg + jb + lane;
            int2 m = make_int2(0, 0);
            if (jb + lane < cnt) m = g_emeta[ge];   // invalid lanes: src=0, norm=0
            int row = (ge >= b1) + (ge >= b2) + (ge >= b3) + (ge >= b4)
                    + (ge >= b5) + (ge >= b6) + (ge >= b7);
            int packed = m.x | (row << 20);
            int nrmi = m.y;
            int jmaxb = min(cnt - jb, 32);
            int npairs = (jmaxb + 1) >> 1;

            int jj = 0;
            for (; jj + 2 <= npairs; jj += 2) {
                int iA = 2 * jj + half, iB = 2 * jj + 2 + half;
                int pkA = __shfl_sync(0xFFFFFFFFu, packed, iA);
                float nnA = __int_as_float(__shfl_sync(0xFFFFFFFFu, nrmi, iA));
                int pkB = __shfl_sync(0xFFFFFFFFu, packed, iB);
                float nnB = __int_as_float(__shfl_sync(0xFFFFFFFFu, nrmi, iB));
                float4 vA = *(const float4*)(X + (size_t)(pkA & 0xFFFFF) * 64 + col4);
                float4 vB = *(const float4*)(X + (size_t)(pkB & 0xFFFFF) * 64 + col4);
                float* apA = abase + ((pkA >> 20) & 7) * ALDA;
                float4 fA = *(float4*)apA;
                fA.x = fmaf(nnA, vA.x, fA.x); fA.y = fmaf(nnA, vA.y, fA.y);
                fA.z = fmaf(nnA, vA.z, fA.z); fA.w = fmaf(nnA, vA.w, fA.w);
                *(float4*)apA = fA;
                float* apB = abase + ((pkB >> 20) & 7) * ALDA;
                float4 fB = *(float4*)apB;
                fB.x = fmaf(nnB, vB.x, fB.x); fB.y = fmaf(nnB, vB.y, fB.y);
                fB.z = fmaf(nnB, vB.z, fB.z); fB.w = fmaf(nnB, vB.w, fB.w);
                *(float4*)apB = fB;
            }
            if (jj < npairs) {
                int iA = 2 * jj + half;
                int pkA = __shfl_sync(0xFFFFFFFFu, packed, iA);
                float nnA = __int_as_float(__shfl_sync(0xFFFFFFFFu, nrmi, iA));
                float4 vA = *(const float4*)(X + (size_t)(pkA & 0xFFFFF) * 64 + col4);
                float* apA = abase + ((pkA >> 20) & 7) * ALDA;
                float4 fA = *(float4*)apA;
                fA.x = fmaf(nnA, vA.x, fA.x); fA.y = fmaf(nnA, vA.y, fA.y);
                fA.z = fmaf(nnA, vA.z, fA.z); fA.w = fmaf(nnA, vA.w, fA.w);
                *(float4*)apA = fA;
            }
        }

        __syncthreads();   // prior chunk's A-fragment reads complete

        // ===== convert: sum banks, fp32 -> bf16 hi/lo tiles =====
        #pragma unroll
        for (int i = 0; i < 8; i++) {
            float2 a0 = *(float2*)(AaccW + i * ALDA + c);
            float2 a1 = *(float2*)(AaccW + (8 + i) * ALDA + c);
            float fx = a0.x + a1.x, fy = a0.y + a1.y;
            __nv_bfloat16 h0, l0, h1, l1;
            split_bf16(fx, h0, l0);
            split_bf16(fy, h1, l1);
            int row = warp * 8 + i;
            __nv_bfloat162 ph; ph.x = h0; ph.y = h1;
            __nv_bfloat162 pl; pl.x = l0; pl.y = l1;
            *(__nv_bfloat162*)(Ahi + row * NLDA + c) = ph;
            *(__nv_bfloat162*)(Alo + row * NLDA + c) = pl;
        }
        __syncthreads();   // tiles ready

        // ===== 3-pass MMA: A via ldmatrix, B via direct global (L1-hot) =====
        #pragma unroll
        for (int ks = 0; ks < 4; ks++) {
            int kbase = r * 64 + ks * 16;
            uint32_t kb = ks * 32;
            uint32_t aH0[4], aH1[4], aL0[4], aL1[4], bH[4], bL[4];
            ldsm4(aH0, aHiAddr + kb);
            ldsm4(aH1, aHiAddr + 16 * (NLDA * 2) + kb);
            ldsm4(aL0, aLoAddr + kb);
            ldsm4(aL1, aLoAddr + 16 * (NLDA * 2) + kb);
            bH[0] = *(const uint32_t*)(Wh0 + kbase);
            bH[1] = *(const uint32_t*)(Wh0 + kbase + 8);
            bH[2] = *(const uint32_t*)(Wh8 + kbase);
            bH[3] = *(const uint32_t*)(Wh8 + kbase + 8);
            bL[0] = *(const uint32_t*)(Wl0 + kbase);
            bL[1] = *(const uint32_t*)(Wl0 + kbase + 8);
            bL[2] = *(const uint32_t*)(Wl8 + kbase);
            bL[3] = *(const uint32_t*)(Wl8 + kbase + 8);
            mma16816(C[0], aH0, bH + 0); mma16816(C[1], aH0, bH + 2);
            mma16816(C[2], aH1, bH + 0); mma16816(C[3], aH1, bH + 2);
            mma16816(C[0], aL0, bH + 0); mma16816(C[1], aL0, bH + 2);
            mma16816(C[2], aL1, bH + 0); mma16816(C[3], aL1, bH + 2);
            mma16816(C[0], aH0, bL + 0); mma16816(C[1], aH0, bL + 2);
            mma16816(C[2], aH1, bL + 0); mma16816(C[3], aH1, bL + 2);
        }
    }

    // ===== epilogue =====
    int dorelu = (phase == 0);
    #pragma unroll
    for (int mt = 0; mt < 2; mt++) {
        int r0 = rb + wr + mt * 16 + g;
        int r1 = r0 + 8;
        #pragma unroll
        for (int nt = 0; nt < 2; nt++) {
            int gc = wc + nt * 8 + 2 * t;
            float b0 = bias[gc], b1 = bias[gc + 1];
            float c00 = C[mt * 2 + nt][0] + b0, c01 = C[mt * 2 + nt][1] + b1;
            float c10 = C[mt * 2 + nt][2] + b0, c11 = C[mt * 2 + nt][3] + b1;
            if (dorelu) {
                c00 = fmaxf(c00, 0.f); c01 = fmaxf(c01, 0.f);
                c10 = fmaxf(c10, 0.f); c11 = fmaxf(c11, 0.f);
            }
            if (r0 < N_NODES)
                *(float2*)(OP + (size_t)r0 * 64 + gc) = make_float2(c00, c01);
            if (r1 < N_NODES)
                *(float2*)(OP + (size_t)r1 * 64 + gc) = make_float2(c10, c11);
        }
    }
}

// ---------------- launch ----------------
extern "C" void kernel_launch(void* const* d_in, const int* in_sizes, int n_in,
                              void* d_out, int out_size) {
    const int* feat = (const int*)d_in[0];
    const int* src = (const int*)d_in[1];
    const int* dst = (const int*)d_in[2];
    const int* etype = (const int*)d_in[3];
    const float* norm = (const float*)d_in[4];
    const float* emb = (const float*)d_in[5];
    const float* smw = (const float*)d_in[6];
    const float* smb = (const float*)d_in[7];
    const float* V1 = (const float*)d_in[8];
    const float* c1 = (const float*)d_in[9];
    const float* b1 = (const float*)d_in[10];
    const float* V2 = (const float*)d_in[11];
    const float* c2 = (const float*)d_in[12];
    const float* b2 = (const float*)d_in[13];
    float* out = (float*)d_out;

    const int smemSM = (128 * NLDA * 2 + 64 * NLDA * 2) * 2 + 128 * 8 * 4;
    const int smemFU = 128 * NLDA * 2 * 2 + 256 * ALDA * 4;   // 36864 + 69632 = 106496
    static int attr_done = 0;
    if (!attr_done) {
        cudaFuncSetAttribute(k_front, cudaFuncAttributeMaxDynamicSharedMemorySize, smemSM);
        cudaFuncSetAttribute(k_fused, cudaFuncAttributeMaxDynamicSharedMemorySize, smemFU);
        attr_done = 1;
    }

    k_front<<<NB_SM + NB_PREPW + NB_HIST, 256, smemSM>>>(feat, emb, smw, smb,
                                                         V1, c1, V2, c2, dst, etype);
    k_scan<<<SCAN_NB, 1024>>>();
    k_scatter<<<NB_HIST, 256>>>(src, dst, etype, norm);
    k_fused<<<NB_SM, 512, smemFU>>>(0, b1, nullptr);      // ncu capture slot
    k_fused<<<NB_SM, 512, smemFU>>>(1, b2, out);
}

// round 9
// speedup vs baseline: 2.0850x; 2.0850x over previous
#include <cuda_runtime.h>
#include <cuda_bf16.h>
#include <stdint.h>

#define N_NODES 100000
#define N_EDGES 1600000
#define NUM_RELS 8
#define H_DIM 64
#define K_TOT 512
#define NSEG (N_NODES * NUM_RELS)          // 800000
#define NLDA 72                            // bf16 elems; 144B row stride (16B aligned)
#define ALDA 64                            // Aacc fp32 leading dim
#define NB_SM 782
#define NB_PREPW 256
#define NB_HIST 6250
#define SCAN_NB 782
#define NB_FU 1563                         // ceil(N_NODES/64)

// ---------------- scratch ----------------
__device__ float g_x[(size_t)N_NODES * H_DIM];
__device__ float g_h[(size_t)N_NODES * H_DIM];
__device__ int   g_cnt[SCAN_NB * 1024];     // zero-init; re-zeroed by scan each run
__device__ int   g_rowptr[NSEG + 1];
__device__ int   g_wp[NSEG];
__device__ unsigned long long g_flags[SCAN_NB];  // zero-init; re-zeroed by scatter
__device__ int2  g_emeta[N_EDGES];          // {src | (dst&7)<<20, norm-bits}
__device__ __align__(16) __nv_bfloat16 g_Wth[2 * H_DIM * K_TOT];   // [layer][o*512 + r*64+k]
__device__ __align__(16) __nv_bfloat16 g_Wtl[2 * H_DIM * K_TOT];

// ---------------- helpers ----------------
__device__ __forceinline__ void mma16816(float* c, const uint32_t* a, const uint32_t* b) {
    asm volatile(
        "mma.sync.aligned.m16n8k16.row.col.f32.bf16.bf16.f32 "
        "{%0,%1,%2,%3}, {%4,%5,%6,%7}, {%8,%9}, {%0,%1,%2,%3};\n"
        : "+f"(c[0]), "+f"(c[1]), "+f"(c[2]), "+f"(c[3])
        : "r"(a[0]), "r"(a[1]), "r"(a[2]), "r"(a[3]), "r"(b[0]), "r"(b[1]));
}

__device__ __forceinline__ void ldsm4(uint32_t* r, uint32_t addr) {
    asm volatile("ldmatrix.sync.aligned.m8n8.x4.shared.b16 {%0,%1,%2,%3}, [%4];"
        : "=r"(r[0]), "=r"(r[1]), "=r"(r[2]), "=r"(r[3]) : "r"(addr));
}

__device__ __forceinline__ void split_bf16(float v, __nv_bfloat16& hi, __nv_bfloat16& lo) {
    hi = __float2bfloat16(v);
    lo = __float2bfloat16(v - __bfloat162float(hi));
}

// ---------------- size matcher body (256 threads/block) ----------------
__device__ void sm_body(int bid, const int* __restrict__ feat, const float* __restrict__ emb,
                        const float* __restrict__ smw, const float* __restrict__ smb,
                        char* smraw) {
    __nv_bfloat16* Ahi = (__nv_bfloat16*)smraw;
    __nv_bfloat16* Alo = Ahi + 128 * NLDA;
    __nv_bfloat16* Bhi = Alo + 128 * NLDA;
    __nv_bfloat16* Blo = Bhi + 64 * NLDA;
    int* sfeat = (int*)(Blo + 64 * NLDA);

    int tid = threadIdx.x;
    int rb = bid * 128;

    for (int idx = tid; idx < 128 * 8; idx += 256) {
        int r = idx >> 3, j = idx & 7;
        sfeat[idx] = (rb + r < N_NODES) ? feat[(size_t)(rb + r) * 8 + j] : 0;
    }

    int lane = tid & 31, warp = tid >> 5;
    int wr = (warp >> 2) * 64;
    int wc = (warp & 3) * 16;
    int g = lane >> 2, t = lane & 3;

    float C[8][4];
    #pragma unroll
    for (int i = 0; i < 8; i++)
        #pragma unroll
        for (int j = 0; j < 4; j++) C[i][j] = 0.f;

    for (int kc = 0; kc < 4; kc++) {
        __syncthreads();
        for (int idx = tid; idx < 128 * 64; idx += 256) {
            int r = idx >> 6, k = idx & 63;
            float v = 0.f;
            if (rb + r < N_NODES) {
                int fid = sfeat[r * 8 + kc * 2 + (k >> 5)];
                v = emb[(size_t)fid * 32 + (k & 31)];
            }
            __nv_bfloat16 h, l; split_bf16(v, h, l);
            Ahi[r * NLDA + k] = h; Alo[r * NLDA + k] = l;
        }
        for (int idx = tid; idx < 64 * 64; idx += 256) {
            int n = idx >> 6, k = idx & 63;
            float v = smw[n * 256 + kc * 64 + k];
            __nv_bfloat16 h, l; split_bf16(v, h, l);
            Bhi[n * NLDA + k] = h; Blo[n * NLDA + k] = l;
        }
        __syncthreads();

        #pragma unroll
        for (int ks = 0; ks < 4; ks++) {
            int k0 = ks * 16;
            #pragma unroll
            for (int p = 0; p < 3; p++) {
                const __nv_bfloat16* As = (p == 1) ? Alo : Ahi;
                const __nv_bfloat16* Bs = (p == 2) ? Blo : Bhi;
                uint32_t a[4][4], b[2][2];
                #pragma unroll
                for (int mt = 0; mt < 4; mt++) {
                    int r0 = wr + mt * 16;
                    a[mt][0] = *(const uint32_t*)(As + (r0 + g) * NLDA + k0 + 2 * t);
                    a[mt][1] = *(const uint32_t*)(As + (r0 + g + 8) * NLDA + k0 + 2 * t);
                    a[mt][2] = *(const uint32_t*)(As + (r0 + g) * NLDA + k0 + 8 + 2 * t);
                    a[mt][3] = *(const uint32_t*)(As + (r0 + g + 8) * NLDA + k0 + 8 + 2 * t);
                }
                #pragma unroll
                for (int nt = 0; nt < 2; nt++) {
                    int c0 = wc + nt * 8 + g;
                    b[nt][0] = *(const uint32_t*)(Bs + c0 * NLDA + k0 + 2 * t);
                    b[nt][1] = *(const uint32_t*)(Bs + c0 * NLDA + k0 + 8 + 2 * t);
                }
                #pragma unroll
                for (int mt = 0; mt < 4; mt++)
                    #pragma unroll
                    for (int nt = 0; nt < 2; nt++)
                        mma16816(C[mt * 2 + nt], a[mt], b[nt]);
            }
        }
    }

    #pragma unroll
    for (int mt = 0; mt < 4; mt++) {
        int r0 = rb + wr + mt * 16 + g;
        int r1 = r0 + 8;
        #pragma unroll
        for (int nt = 0; nt < 2; nt++) {
            int gc = wc + nt * 8 + 2 * t;
            float b0 = smb[gc], b1 = smb[gc + 1];
            if (r0 < N_NODES)
                *(float2*)(g_x + (size_t)r0 * 64 + gc) =
                    make_float2(C[mt * 2 + nt][0] + b0, C[mt * 2 + nt][1] + b1);
            if (r1 < N_NODES)
                *(float2*)(g_x + (size_t)r1 * 64 + gc) =
                    make_float2(C[mt * 2 + nt][2] + b0, C[mt * 2 + nt][3] + b1);
        }
    }
}

// ---------------- front kernel: sm + prepw + hist ----------------
__global__ void k_front(const int* __restrict__ feat, const float* __restrict__ emb,
                        const float* __restrict__ smw, const float* __restrict__ smb,
                        const float* __restrict__ V1, const float* __restrict__ c1,
                        const float* __restrict__ V2, const float* __restrict__ c2,
                        const int* __restrict__ dst, const int* __restrict__ etype) {
    extern __shared__ char smraw[];
    int bid = blockIdx.x;
    if (bid < NB_SM) {
        sm_body(bid, feat, emb, smw, smb, smraw);
    } else if (bid < NB_SM + NB_PREPW) {
        int t = (bid - NB_SM) * 256 + threadIdx.x;
        int sel = t >= H_DIM * K_TOT;
        int u = t & (H_DIM * K_TOT - 1);
        int o = u >> 9;
        int c = u & 511;
        int r = c >> 6, k = c & 63;
        const float* V = sel ? V2 : V1;
        const float* cp = sel ? c2 : c1;
        float s = 0.f;
        #pragma unroll
        for (int b = 0; b < 8; b++)
            s += cp[r * 8 + b] * V[(b * 64 + k) * 64 + o];
        __nv_bfloat16 hi = __float2bfloat16(s);
        __nv_bfloat16 lo = __float2bfloat16(s - __bfloat162float(hi));
        g_Wth[t] = hi;
        g_Wtl[t] = lo;
    } else {
        int e = (bid - NB_SM - NB_PREPW) * 256 + threadIdx.x;
        if (e < N_EDGES)
            atomicAdd(&g_cnt[etype[e] * N_NODES + dst[e]], 1);
    }
}

// ---------------- single-kernel scan (decoupled lookback) ----------------
__global__ __launch_bounds__(1024) void k_scan() {
    __shared__ int wsum[32];
    __shared__ int s_excl;
    int tid = threadIdx.x, b = blockIdx.x;
    int i = b * 1024 + tid;
    int v = (i < NSEG) ? g_cnt[i] : 0;
    int lane = tid & 31, wid = tid >> 5;
    int s = v;
    #pragma unroll
    for (int d = 1; d < 32; d <<= 1) {
        int t = __shfl_up_sync(0xFFFFFFFFu, s, d);
        if (lane >= d) s += t;
    }
    if (lane == 31) wsum[wid] = s;
    __syncthreads();
    if (wid == 0) {
        int ws = wsum[lane];
        #pragma unroll
        for (int d = 1; d < 32; d <<= 1) {
            int t = __shfl_up_sync(0xFFFFFFFFu, ws, d);
            if (lane >= d) ws += t;
        }
        wsum[lane] = ws;
    }
    __syncthreads();
    int incl = s + ((wid > 0) ? wsum[wid - 1] : 0);
    int total = wsum[31];

    if (tid == 0) {
        unsigned long long f =
            ((unsigned long long)((b == 0) ? 2u : 1u) << 32) | (unsigned)total;
        atomicExch(&g_flags[b], f);
        if (b == 0) s_excl = 0;
    }
    if (b > 0 && wid == 0) {
        int running = 0;
        int p = b - 1;
        while (true) {
            int idx = p - lane;
            unsigned long long f = (idx >= 0) ? atomicOr(&g_flags[idx], 0ULL)
                                              : (2ULL << 32);
            unsigned st = (unsigned)(f >> 32);
            if (__ballot_sync(0xFFFFFFFFu, st == 0)) continue;
            unsigned b2 = __ballot_sync(0xFFFFFFFFu, st == 2);
            int val = (int)(unsigned)f;
            if (b2) {
                int k = __ffs(b2) - 1;
                int contrib = (lane <= k) ? val : 0;
                #pragma unroll
                for (int off = 16; off > 0; off >>= 1)
                    contrib += __shfl_xor_sync(0xFFFFFFFFu, contrib, off);
                running += contrib;
                break;
            } else {
                int contrib = val;
                #pragma unroll
                for (int off = 16; off > 0; off >>= 1)
                    contrib += __shfl_xor_sync(0xFFFFFFFFu, contrib, off);
                running += contrib;
                p -= 32;
            }
        }
        if (lane == 0) {
            s_excl = running;
            unsigned long long f = (2ULL << 32) | (unsigned)(running + total);
            atomicExch(&g_flags[b], f);
        }
    }
    __syncthreads();
    int rp = s_excl + incl - v;
    if (i < NSEG) {
        g_rowptr[i] = rp;
        g_wp[i] = rp;
        g_cnt[i] = 0;
    }
    if (i == NSEG - 1) g_rowptr[NSEG] = rp + v;
}

// ---------------- scatter (packs row = dst&7; re-zeroes g_flags) ----------------
__global__ void k_scatter(const int* __restrict__ src, const int* __restrict__ dst,
                          const int* __restrict__ etype, const float* __restrict__ norm) {
    int gid = blockIdx.x * blockDim.x + threadIdx.x;
    if (gid < SCAN_NB) g_flags[gid] = 0ULL;
    if (gid >= N_EDGES) return;
    int d = dst[gid];
    int seg = etype[gid] * N_NODES + d;
    int p = atomicAdd(&g_wp[seg], 1);
    g_emeta[p] = make_int2(src[gid] | ((d & 7) << 20), __float_as_int(norm[gid]));
}

// ---------------- fused layer v5: 64-node blocks, paired halves, B smem uint4 ------
__global__ __launch_bounds__(256, 3)
void k_fused(int phase, const float* __restrict__ bias, float* __restrict__ dout) {
    const float* __restrict__ X = phase ? g_h : g_x;
    float* __restrict__ OP = phase ? dout : g_h;
    const __nv_bfloat16* __restrict__ Wh = g_Wth + phase * H_DIM * K_TOT;
    const __nv_bfloat16* __restrict__ Wl = g_Wtl + phase * H_DIM * K_TOT;

    extern __shared__ char smraw[];
    __nv_bfloat16* Ahi = (__nv_bfloat16*)smraw;         // 64*72  (9216 B)
    __nv_bfloat16* Alo = Ahi + 64 * NLDA;               // 9216 B
    __nv_bfloat16* Bhi = Alo + 64 * NLDA;               // 9216 B
    __nv_bfloat16* Blo = Bhi + 64 * NLDA;               // 9216 B
    float* Aacc = (float*)(Blo + 64 * NLDA);            // 128 rows * 64 fp32 (32768 B)

    int tid = threadIdx.x;
    int rb = blockIdx.x * 64;
    int lane = tid & 31, warp = tid >> 5;       // 8 warps
    int c = lane * 2;
    int half = lane >> 4;
    int col4 = (lane & 15) * 4;

    int wr = (warp >> 2) * 32;                  // 0 or 32
    int wc = (warp & 3) * 16;                   // 0,16,32,48
    int g = lane >> 2, t = lane & 3;

    // ldmatrix per-lane addresses (mapping validated in R7)
    int rowA = (lane & 7) + ((lane >> 3) & 1) * 8;
    int colA = ((lane >> 4) & 1) * 8;
    int rowB = (lane & 7) + ((lane >> 4) & 1) * 8;
    int colB = ((lane >> 3) & 1) * 8;
    uint32_t aHiAddr = (uint32_t)__cvta_generic_to_shared(Ahi) + (wr + rowA) * (NLDA * 2) + colA * 2;
    uint32_t aLoAddr = (uint32_t)__cvta_generic_to_shared(Alo) + (wr + rowA) * (NLDA * 2) + colA * 2;
    uint32_t bHiAddr = (uint32_t)__cvta_generic_to_shared(Bhi) + (wc + rowB) * (NLDA * 2) + colB * 2;
    uint32_t bLoAddr = (uint32_t)__cvta_generic_to_shared(Blo) + (wc + rowB) * (NLDA * 2) + colB * 2;

    float* AaccW = Aacc + (warp * 16) * ALDA;       // 16-row slab: bank0 rows 0-7, bank1 rows 8-15
    float* abase = AaccW + (half * 8) * ALDA + col4;

    float C[4][4];
    #pragma unroll
    for (int i = 0; i < 4; i++)
        #pragma unroll
        for (int j = 0; j < 4; j++) C[i][j] = 0.f;

    for (int r = 0; r < NUM_RELS; r++) {
        // ===== zero own bank rows =====
        #pragma unroll
        for (int i = 0; i < 8; i++)
            *(float4*)(abase + i * ALDA) = make_float4(0.f, 0.f, 0.f, 0.f);

        // ===== warp edge range =====
        int segbase = r * N_NODES + rb + warp * 8;
        int clampmax = r * N_NODES + N_NODES;
        int bp = 0;
        if (lane <= 8) bp = g_rowptr[min(segbase + lane, clampmax)];
        int wbeg = __shfl_sync(0xFFFFFFFFu, bp, 0);
        int wend = __shfl_sync(0xFFFFFFFFu, bp, 8);
        int cnt = wend - wbeg;

        // ===== aggregation: 2 edges per warp-instruction (halves) =====
        for (int jb = 0; jb < cnt; jb += 32) {
            int ge = wbeg + jb + lane;
            int2 m = make_int2(0, 0);
            if (jb + lane < cnt) m = g_emeta[ge];   // dummy lanes: src=0,row=0,norm=0
            int packed = m.x;
            int nrmi = m.y;
            int jmaxb = min(cnt - jb, 32);
            int npairs2 = ((jmaxb + 1) >> 1);
            npairs2 = (npairs2 + 1) & ~1;           // round up to even (dummies harmless)

            for (int jj = 0; jj < npairs2; jj += 2) {
                int iA = 2 * jj + half, iB = 2 * jj + 2 + half;
                int pkA = __shfl_sync(0xFFFFFFFFu, packed, iA);
                float nnA = __int_as_float(__shfl_sync(0xFFFFFFFFu, nrmi, iA));
                int pkB = __shfl_sync(0xFFFFFFFFu, packed, iB);
                float nnB = __int_as_float(__shfl_sync(0xFFFFFFFFu, nrmi, iB));
                float4 vA = *(const float4*)(X + (size_t)(pkA & 0xFFFFF) * 64 + col4);
                float4 vB = *(const float4*)(X + (size_t)(pkB & 0xFFFFF) * 64 + col4);
                float* apA = abase + ((pkA >> 20) & 7) * ALDA;
                float4 fA = *(float4*)apA;
                fA.x = fmaf(nnA, vA.x, fA.x); fA.y = fmaf(nnA, vA.y, fA.y);
                fA.z = fmaf(nnA, vA.z, fA.z); fA.w = fmaf(nnA, vA.w, fA.w);
                *(float4*)apA = fA;
                float* apB = abase + ((pkB >> 20) & 7) * ALDA;
                float4 fB = *(float4*)apB;
                fB.x = fmaf(nnB, vB.x, fB.x); fB.y = fmaf(nnB, vB.y, fB.y);
                fB.z = fmaf(nnB, vB.z, fB.z); fB.w = fmaf(nnB, vB.w, fB.w);
                *(float4*)apB = fB;
            }
        }

        __syncthreads();   // prior chunk's fragment reads (A and B tiles) complete

        // ===== convert: sum banks -> bf16 hi/lo tiles (own 8 rows) =====
        #pragma unroll
        for (int i = 0; i < 8; i++) {
            float2 a0 = *(float2*)(AaccW + i * ALDA + c);
            float2 a1 = *(float2*)(AaccW + (8 + i) * ALDA + c);
            float fx = a0.x + a1.x, fy = a0.y + a1.y;
            __nv_bfloat16 h0, l0, h1, l1;
            split_bf16(fx, h0, l0);
            split_bf16(fy, h1, l1);
            int row = warp * 8 + i;
            __nv_bfloat162 ph; ph.x = h0; ph.y = h1;
            __nv_bfloat162 pl; pl.x = l0; pl.y = l1;
            *(__nv_bfloat162*)(Ahi + row * NLDA + c) = ph;
            *(__nv_bfloat162*)(Alo + row * NLDA + c) = pl;
        }

        // ===== B chunk copy, vectorized (2 uint4 per thread per array) =====
        for (int idx = tid; idx < 512; idx += 256) {
            int n = idx >> 3;
            int k8 = (idx & 7) * 8;
            *(uint4*)(Bhi + n * NLDA + k8) = *(const uint4*)(Wh + n * K_TOT + r * 64 + k8);
            *(uint4*)(Blo + n * NLDA + k8) = *(const uint4*)(Wl + n * K_TOT + r * 64 + k8);
        }
        __syncthreads();   // tiles ready

        // ===== 3-pass MMA via ldmatrix =====
        #pragma unroll
        for (int ks = 0; ks < 4; ks++) {
            uint32_t kb = ks * 32;
            uint32_t aH0[4], aH1[4], aL0[4], aL1[4], bH[4], bL[4];
            ldsm4(aH0, aHiAddr + kb);
            ldsm4(aH1, aHiAddr + 16 * (NLDA * 2) + kb);
            ldsm4(aL0, aLoAddr + kb);
            ldsm4(aL1, aLoAddr + 16 * (NLDA * 2) + kb);
            ldsm4(bH, bHiAddr + kb);
            ldsm4(bL, bLoAddr + kb);
            mma16816(C[0], aH0, bH + 0); mma16816(C[1], aH0, bH + 2);
            mma16816(C[2], aH1, bH + 0); mma16816(C[3], aH1, bH + 2);
            mma16816(C[0], aL0, bH + 0); mma16816(C[1], aL0, bH + 2);
            mma16816(C[2], aL1, bH + 0); mma16816(C[3], aL1, bH + 2);
            mma16816(C[0], aH0, bL + 0); mma16816(C[1], aH0, bL + 2);
            mma16816(C[2], aH1, bL + 0); mma16816(C[3], aH1, bL + 2);
        }
    }

    // ===== epilogue =====
    int dorelu = (phase == 0);
    #pragma unroll
    for (int mt = 0; mt < 2; mt++) {
        int r0 = rb + wr + mt * 16 + g;
        int r1 = r0 + 8;
        #pragma unroll
        for (int nt = 0; nt < 2; nt++) {
            int gc = wc + nt * 8 + 2 * t;
            float b0 = bias[gc], b1 = bias[gc + 1];
            float c00 = C[mt * 2 + nt][0] + b0, c01 = C[mt * 2 + nt][1] + b1;
            float c10 = C[mt * 2 + nt][2] + b0, c11 = C[mt * 2 + nt][3] + b1;
            if (dorelu) {
                c00 = fmaxf(c00, 0.f); c01 = fmaxf(c01, 0.f);
                c10 = fmaxf(c10, 0.f); c11 = fmaxf(c11, 0.f);
            }
            if (r0 < N_NODES)
                *(float2*)(OP + (size_t)r0 * 64 + gc) = make_float2(c00, c01);
            if (r1 < N_NODES)
                *(float2*)(OP + (size_t)r1 * 64 + gc) = make_float2(c10, c11);
        }
    }
}

// ---------------- launch ----------------
extern "C" void kernel_launch(void* const* d_in, const int* in_sizes, int n_in,
                              void* d_out, int out_size) {
    const int* feat = (const int*)d_in[0];
    const int* src = (const int*)d_in[1];
    const int* dst = (const int*)d_in[2];
    const int* etype = (const int*)d_in[3];
    const float* norm = (const float*)d_in[4];
    const float* emb = (const float*)d_in[5];
    const float* smw = (const float*)d_in[6];
    const float* smb = (const float*)d_in[7];
    const float* V1 = (const float*)d_in[8];
    const float* c1 = (const float*)d_in[9];
    const float* b1 = (const float*)d_in[10];
    const float* V2 = (const float*)d_in[11];
    const float* c2 = (const float*)d_in[12];
    const float* b2 = (const float*)d_in[13];
    float* out = (float*)d_out;

    const int smemSM = (128 * NLDA * 2 + 64 * NLDA * 2) * 2 + 128 * 8 * 4;
    const int smemFU = 64 * NLDA * 2 * 4 + 128 * ALDA * 4;   // 36864 + 32768 = 69632
    static int attr_done = 0;
    if (!attr_done) {
        cudaFuncSetAttribute(k_front, cudaFuncAttributeMaxDynamicSharedMemorySize, smemSM);
        cudaFuncSetAttribute(k_fused, cudaFuncAttributeMaxDynamicSharedMemorySize, smemFU);
        attr_done = 1;
    }

    k_front<<<NB_SM + NB_PREPW + NB_HIST, 256, smemSM>>>(feat, emb, smw, smb,
                                                         V1, c1, V2, c2, dst, etype);
    k_scan<<<SCAN_NB, 1024>>>();
    k_scatter<<<NB_HIST, 256>>>(src, dst, etype, norm);
    k_fused<<<NB_FU, 256, smemFU>>>(0, b1, nullptr);      // ncu capture slot
    k_fused<<<NB_FU, 256, smemFU>>>(1, b2, out);
}

// round 10
// speedup vs baseline: 2.0852x; 1.0001x over previous
#include <cuda_runtime.h>
#include <cuda_bf16.h>
#include <stdint.h>

#define N_NODES 100000
#define N_EDGES 1600000
#define NUM_RELS 8
#define H_DIM 64
#define K_TOT 512
#define NSEG (N_NODES * NUM_RELS)          // 800000
#define NLDA 72                            // bf16 elems; 144B row stride (16B aligned)
#define ALDA 64                            // Aacc fp32 leading dim (256B rows)
#define NB_SM 782
#define NB_PREPW 256
#define NB_HIST 6250
#define SCAN_NB 782
#define NB_FU 1563                         // ceil(N_NODES/64)

// ---------------- scratch ----------------
__device__ float g_x[(size_t)N_NODES * H_DIM];
__device__ float g_h[(size_t)N_NODES * H_DIM];
__device__ int   g_cnt[SCAN_NB * 1024];     // zero-init; re-zeroed by scan each run
__device__ int   g_rowptr[NSEG + 1];
__device__ int   g_wp[NSEG];
__device__ unsigned long long g_flags[SCAN_NB];  // zero-init; re-zeroed by scatter
__device__ int2  g_emeta[N_EDGES];          // {src | (dst&7)<<20, norm-bits}
__device__ __align__(16) __nv_bfloat16 g_Wth[2 * H_DIM * K_TOT];   // [layer][o*512 + r*64+k]
__device__ __align__(16) __nv_bfloat16 g_Wtl[2 * H_DIM * K_TOT];

// ---------------- helpers ----------------
__device__ __forceinline__ void mma16816(float* c, const uint32_t* a, const uint32_t* b) {
    asm volatile(
        "mma.sync.aligned.m16n8k16.row.col.f32.bf16.bf16.f32 "
        "{%0,%1,%2,%3}, {%4,%5,%6,%7}, {%8,%9}, {%0,%1,%2,%3};\n"
        : "+f"(c[0]), "+f"(c[1]), "+f"(c[2]), "+f"(c[3])
        : "r"(a[0]), "r"(a[1]), "r"(a[2]), "r"(a[3]), "r"(b[0]), "r"(b[1]));
}

__device__ __forceinline__ void ldsm4(uint32_t* r, uint32_t addr) {
    asm volatile("ldmatrix.sync.aligned.m8n8.x4.shared.b16 {%0,%1,%2,%3}, [%4];"
        : "=r"(r[0]), "=r"(r[1]), "=r"(r[2]), "=r"(r[3]) : "r"(addr));
}

// predicated 128-bit smem store: fires only when cond != 0 (no BSSY/branch)
__device__ __forceinline__ void sts128_pred(uint32_t addr, float4 v, int cond) {
    asm volatile(
        "{\n\t.reg .pred p;\n\t"
        "setp.ne.s32 p, %5, 0;\n\t"
        "@p st.shared.v4.f32 [%0], {%1,%2,%3,%4};\n\t}"
        :: "r"(addr), "f"(v.x), "f"(v.y), "f"(v.z), "f"(v.w), "r"(cond) : "memory");
}

__device__ __forceinline__ void split_bf16(float v, __nv_bfloat16& hi, __nv_bfloat16& lo) {
    hi = __float2bfloat16(v);
    lo = __float2bfloat16(v - __bfloat162float(hi));
}

// ---------------- size matcher body (256 threads/block) ----------------
__device__ void sm_body(int bid, const int* __restrict__ feat, const float* __restrict__ emb,
                        const float* __restrict__ smw, const float* __restrict__ smb,
                        char* smraw) {
    __nv_bfloat16* Ahi = (__nv_bfloat16*)smraw;
    __nv_bfloat16* Alo = Ahi + 128 * NLDA;
    __nv_bfloat16* Bhi = Alo + 128 * NLDA;
    __nv_bfloat16* Blo = Bhi + 64 * NLDA;
    int* sfeat = (int*)(Blo + 64 * NLDA);

    int tid = threadIdx.x;
    int rb = bid * 128;

    for (int idx = tid; idx < 128 * 8; idx += 256) {
        int r = idx >> 3, j = idx & 7;
        sfeat[idx] = (rb + r < N_NODES) ? feat[(size_t)(rb + r) * 8 + j] : 0;
    }

    int lane = tid & 31, warp = tid >> 5;
    int wr = (warp >> 2) * 64;
    int wc = (warp & 3) * 16;
    int g = lane >> 2, t = lane & 3;

    float C[8][4];
    #pragma unroll
    for (int i = 0; i < 8; i++)
        #pragma unroll
        for (int j = 0; j < 4; j++) C[i][j] = 0.f;

    for (int kc = 0; kc < 4; kc++) {
        __syncthreads();
        for (int idx = tid; idx < 128 * 64; idx += 256) {
            int r = idx >> 6, k = idx & 63;
            float v = 0.f;
            if (rb + r < N_NODES) {
                int fid = sfeat[r * 8 + kc * 2 + (k >> 5)];
                v = emb[(size_t)fid * 32 + (k & 31)];
            }
            __nv_bfloat16 h, l; split_bf16(v, h, l);
            Ahi[r * NLDA + k] = h; Alo[r * NLDA + k] = l;
        }
        for (int idx = tid; idx < 64 * 64; idx += 256) {
            int n = idx >> 6, k = idx & 63;
            float v = smw[n * 256 + kc * 64 + k];
            __nv_bfloat16 h, l; split_bf16(v, h, l);
            Bhi[n * NLDA + k] = h; Blo[n * NLDA + k] = l;
        }
        __syncthreads();

        #pragma unroll
        for (int ks = 0; ks < 4; ks++) {
            int k0 = ks * 16;
            #pragma unroll
            for (int p = 0; p < 3; p++) {
                const __nv_bfloat16* As = (p == 1) ? Alo : Ahi;
                const __nv_bfloat16* Bs = (p == 2) ? Blo : Bhi;
                uint32_t a[4][4], b[2][2];
                #pragma unroll
                for (int mt = 0; mt < 4; mt++) {
                    int r0 = wr + mt * 16;
                    a[mt][0] = *(const uint32_t*)(As + (r0 + g) * NLDA + k0 + 2 * t);
                    a[mt][1] = *(const uint32_t*)(As + (r0 + g + 8) * NLDA + k0 + 2 * t);
                    a[mt][2] = *(const uint32_t*)(As + (r0 + g) * NLDA + k0 + 8 + 2 * t);
                    a[mt][3] = *(const uint32_t*)(As + (r0 + g + 8) * NLDA + k0 + 8 + 2 * t);
                }
                #pragma unroll
                for (int nt = 0; nt < 2; nt++) {
                    int c0 = wc + nt * 8 + g;
                    b[nt][0] = *(const uint32_t*)(Bs + c0 * NLDA + k0 + 2 * t);
                    b[nt][1] = *(const uint32_t*)(Bs + c0 * NLDA + k0 + 8 + 2 * t);
                }
                #pragma unroll
                for (int mt = 0; mt < 4; mt++)
                    #pragma unroll
                    for (int nt = 0; nt < 2; nt++)
                        mma16816(C[mt * 2 + nt], a[mt], b[nt]);
            }
        }
    }

    #pragma unroll
    for (int mt = 0; mt < 4; mt++) {
        int r0 = rb + wr + mt * 16 + g;
        int r1 = r0 + 8;
        #pragma unroll
        for (int nt = 0; nt < 2; nt++) {
            int gc = wc + nt * 8 + 2 * t;
            float b0 = smb[gc], b1 = smb[gc + 1];
            if (r0 < N_NODES)
                *(float2*)(g_x + (size_t)r0 * 64 + gc) =
                    make_float2(C[mt * 2 + nt][0] + b0, C[mt * 2 + nt][1] + b1);
            if (r1 < N_NODES)
                *(float2*)(g_x + (size_t)r1 * 64 + gc) =
                    make_float2(C[mt * 2 + nt][2] + b0, C[mt * 2 + nt][3] + b1);
        }
    }
}

// ---------------- front kernel: sm + prepw + hist ----------------
__global__ void k_front(const int* __restrict__ feat, const float* __restrict__ emb,
                        const float* __restrict__ smw, const float* __restrict__ smb,
                        const float* __restrict__ V1, const float* __restrict__ c1,
                        const float* __restrict__ V2, const float* __restrict__ c2,
                        const int* __restrict__ dst, const int* __restrict__ etype) {
    extern __shared__ char smraw[];
    int bid = blockIdx.x;
    if (bid < NB_SM) {
        sm_body(bid, feat, emb, smw, smb, smraw);
    } else if (bid < NB_SM + NB_PREPW) {
        int t = (bid - NB_SM) * 256 + threadIdx.x;
        int sel = t >= H_DIM * K_TOT;
        int u = t & (H_DIM * K_TOT - 1);
        int o = u >> 9;
        int c = u & 511;
        int r = c >> 6, k = c & 63;
        const float* V = sel ? V2 : V1;
        const float* cp = sel ? c2 : c1;
        float s = 0.f;
        #pragma unroll
        for (int b = 0; b < 8; b++)
            s += cp[r * 8 + b] * V[(b * 64 + k) * 64 + o];
        __nv_bfloat16 hi = __float2bfloat16(s);
        __nv_bfloat16 lo = __float2bfloat16(s - __bfloat162float(hi));
        g_Wth[t] = hi;
        g_Wtl[t] = lo;
    } else {
        int e = (bid - NB_SM - NB_PREPW) * 256 + threadIdx.x;
        if (e < N_EDGES)
            atomicAdd(&g_cnt[etype[e] * N_NODES + dst[e]], 1);
    }
}

// ---------------- single-kernel scan (decoupled lookback) ----------------
__global__ __launch_bounds__(1024) void k_scan() {
    __shared__ int wsum[32];
    __shared__ int s_excl;
    int tid = threadIdx.x, b = blockIdx.x;
    int i = b * 1024 + tid;
    int v = (i < NSEG) ? g_cnt[i] : 0;
    int lane = tid & 31, wid = tid >> 5;
    int s = v;
    #pragma unroll
    for (int d = 1; d < 32; d <<= 1) {
        int t = __shfl_up_sync(0xFFFFFFFFu, s, d);
        if (lane >= d) s += t;
    }
    if (lane == 31) wsum[wid] = s;
    __syncthreads();
    if (wid == 0) {
        int ws = wsum[lane];
        #pragma unroll
        for (int d = 1; d < 32; d <<= 1) {
            int t = __shfl_up_sync(0xFFFFFFFFu, ws, d);
            if (lane >= d) ws += t;
        }
        wsum[lane] = ws;
    }
    __syncthreads();
    int incl = s + ((wid > 0) ? wsum[wid - 1] : 0);
    int total = wsum[31];

    if (tid == 0) {
        unsigned long long f =
            ((unsigned long long)((b == 0) ? 2u : 1u) << 32) | (unsigned)total;
        atomicExch(&g_flags[b], f);
        if (b == 0) s_excl = 0;
    }
    if (b > 0 && wid == 0) {
        int running = 0;
        int p = b - 1;
        while (true) {
            int idx = p - lane;
            unsigned long long f = (idx >= 0) ? atomicOr(&g_flags[idx], 0ULL)
                                              : (2ULL << 32);
            unsigned st = (unsigned)(f >> 32);
            if (__ballot_sync(0xFFFFFFFFu, st == 0)) continue;
            unsigned b2 = __ballot_sync(0xFFFFFFFFu, st == 2);
            int val = (int)(unsigned)f;
            if (b2) {
                int k = __ffs(b2) - 1;
                int contrib = (lane <= k) ? val : 0;
                #pragma unroll
                for (int off = 16; off > 0; off >>= 1)
                    contrib += __shfl_xor_sync(0xFFFFFFFFu, contrib, off);
                running += contrib;
                break;
            } else {
                int contrib = val;
                #pragma unroll
                for (int off = 16; off > 0; off >>= 1)
                    contrib += __shfl_xor_sync(0xFFFFFFFFu, contrib, off);
                running += contrib;
                p -= 32;
            }
        }
        if (lane == 0) {
            s_excl = running;
            unsigned long long f = (2ULL << 32) | (unsigned)(running + total);
            atomicExch(&g_flags[b], f);
        }
    }
    __syncthreads();
    int rp = s_excl + incl - v;
    if (i < NSEG) {
        g_rowptr[i] = rp;
        g_wp[i] = rp;
        g_cnt[i] = 0;
    }
    if (i == NSEG - 1) g_rowptr[NSEG] = rp + v;
}

// ---------------- scatter (packs row = dst&7; re-zeroes g_flags) ----------------
__global__ void k_scatter(const int* __restrict__ src, const int* __restrict__ dst,
                          const int* __restrict__ etype, const float* __restrict__ norm) {
    int gid = blockIdx.x * blockDim.x + threadIdx.x;
    if (gid < SCAN_NB) g_flags[gid] = 0ULL;
    if (gid >= N_EDGES) return;
    int d = dst[gid];
    int seg = etype[gid] * N_NODES + d;
    int p = atomicAdd(&g_wp[seg], 1);
    g_emeta[p] = make_int2(src[gid] | ((d & 7) << 20), __float_as_int(norm[gid]));
}

// ---------------- fused layer v6: run-flush aggregation (sorted rows) --------------
__global__ __launch_bounds__(256, 3)
void k_fused(int phase, const float* __restrict__ bias, float* __restrict__ dout) {
    const float* __restrict__ X = phase ? g_h : g_x;
    float* __restrict__ OP = phase ? dout : g_h;
    const __nv_bfloat16* __restrict__ Wh = g_Wth + phase * H_DIM * K_TOT;
    const __nv_bfloat16* __restrict__ Wl = g_Wtl + phase * H_DIM * K_TOT;

    extern __shared__ char smraw[];
    __nv_bfloat16* Ahi = (__nv_bfloat16*)smraw;         // 64*72  (9216 B)
    __nv_bfloat16* Alo = Ahi + 64 * NLDA;               // 9216 B
    __nv_bfloat16* Bhi = Alo + 64 * NLDA;               // 9216 B
    __nv_bfloat16* Blo = Bhi + 64 * NLDA;               // 9216 B
    float* Aacc = (float*)(Blo + 64 * NLDA);            // 128 rows * 64 fp32 (32768 B)

    int tid = threadIdx.x;
    int rb = blockIdx.x * 64;
    int lane = tid & 31, warp = tid >> 5;       // 8 warps
    int c = lane * 2;
    int half = lane >> 4;
    int col4 = (lane & 15) * 4;

    int wr = (warp >> 2) * 32;                  // 0 or 32
    int wc = (warp & 3) * 16;                   // 0,16,32,48
    int g = lane >> 2, t = lane & 3;

    // ldmatrix per-lane addresses (mapping validated in R7)
    int rowA = (lane & 7) + ((lane >> 3) & 1) * 8;
    int colA = ((lane >> 4) & 1) * 8;
    int rowB = (lane & 7) + ((lane >> 4) & 1) * 8;
    int colB = ((lane >> 3) & 1) * 8;
    uint32_t aHiAddr = (uint32_t)__cvta_generic_to_shared(Ahi) + (wr + rowA) * (NLDA * 2) + colA * 2;
    uint32_t aLoAddr = (uint32_t)__cvta_generic_to_shared(Alo) + (wr + rowA) * (NLDA * 2) + colA * 2;
    uint32_t bHiAddr = (uint32_t)__cvta_generic_to_shared(Bhi) + (wc + rowB) * (NLDA * 2) + colB * 2;
    uint32_t bLoAddr = (uint32_t)__cvta_generic_to_shared(Blo) + (wc + rowB) * (NLDA * 2) + colB * 2;

    float* AaccW = Aacc + (warp * 16) * ALDA;       // 16-row slab: bank0 rows 0-7, bank1 rows 8-15
    float* abase = AaccW + (half * 8) * ALDA + col4;
    uint32_t abaseAddr = (uint32_t)__cvta_generic_to_shared(abase);

    float C[4][4];
    #pragma unroll
    for (int i = 0; i < 4; i++)
        #pragma unroll
        for (int j = 0; j < 4; j++) C[i][j] = 0.f;

    for (int r = 0; r < NUM_RELS; r++) {
        // ===== zero own bank rows =====
        #pragma unroll
        for (int i = 0; i < 8; i++)
            *(float4*)(abase + i * ALDA) = make_float4(0.f, 0.f, 0.f, 0.f);

        // ===== warp edge range =====
        int segbase = r * N_NODES + rb + warp * 8;
        int clampmax = r * N_NODES + N_NODES;
        int bp = 0;
        if (lane <= 8) bp = g_rowptr[min(segbase + lane, clampmax)];
        int wbeg = __shfl_sync(0xFFFFFFFFu, bp, 0);
        int wend = __shfl_sync(0xFFFFFFFFu, bp, 8);
        int cnt = wend - wbeg;

        // ===== aggregation: run-flush over this half's sorted edge stream =====
        // Half h owns edges wbeg+h, wbeg+h+2, ... Rows are non-decreasing along
        // the stream, so each row is one contiguous run: accumulate in regs,
        // pure-store on row change (predicated STS — no branch), final store at end.
        {
            float4 acc = make_float4(0.f, 0.f, 0.f, 0.f);
            int cur = 0;
            int jmax = (cnt + 1) >> 1;         // pairs per half (uniform bound)
            int eBase = wbeg + half;
            int eLast = wend - 1;
            for (int j = 0; j < jmax; j += 2) {
                int e0 = eBase + 2 * j;
                int e1 = e0 + 2;
                int2 m0 = g_emeta[min(e0, eLast)];    // broadcast within half (L1 hit)
                int2 m1 = g_emeta[min(e1, eLast)];
                float nn0 = (e0 < wend) ? __int_as_float(m0.y) : 0.f;
                float nn1 = (e1 < wend) ? __int_as_float(m1.y) : 0.f;
                float4 v0 = *(const float4*)(X + (size_t)(m0.x & 0xFFFFF) * 64 + col4);
                float4 v1 = *(const float4*)(X + (size_t)(m1.x & 0xFFFFF) * 64 + col4);
                int rw0 = (m0.x >> 20) & 7;
                int rw1 = (m1.x >> 20) & 7;

                int fl0 = rw0 - cur;                      // >0 on row change (sorted)
                sts128_pred(abaseAddr + cur * 256, acc, fl0);
                acc.x = fl0 ? 0.f : acc.x; acc.y = fl0 ? 0.f : acc.y;
                acc.z = fl0 ? 0.f : acc.z; acc.w = fl0 ? 0.f : acc.w;
                cur = rw0;
                acc.x = fmaf(nn0, v0.x, acc.x); acc.y = fmaf(nn0, v0.y, acc.y);
                acc.z = fmaf(nn0, v0.z, acc.z); acc.w = fmaf(nn0, v0.w, acc.w);

                int fl1 = rw1 - cur;
                sts128_pred(abaseAddr + cur * 256, acc, fl1);
                acc.x = fl1 ? 0.f : acc.x; acc.y = fl1 ? 0.f : acc.y;
                acc.z = fl1 ? 0.f : acc.z; acc.w = fl1 ? 0.f : acc.w;
                cur = rw1;
                acc.x = fmaf(nn1, v1.x, acc.x); acc.y = fmaf(nn1, v1.y, acc.y);
                acc.z = fmaf(nn1, v1.z, acc.z); acc.w = fmaf(nn1, v1.w, acc.w);
            }
            // final flush (cnt==0 -> stores zeros over pre-zeroed row 0: harmless)
            *(float4*)(abase + cur * ALDA) = acc;
        }

        __syncthreads();   // prior chunk's fragment reads + this chunk's Aacc ready

        // ===== convert: sum banks -> bf16 hi/lo tiles (own 8 rows) =====
        #pragma unroll
        for (int i = 0; i < 8; i++) {
            float2 a0 = *(float2*)(AaccW + i * ALDA + c);
            float2 a1 = *(float2*)(AaccW + (8 + i) * ALDA + c);
            float fx = a0.x + a1.x, fy = a0.y + a1.y;
            __nv_bfloat16 h0, l0, h1, l1;
            split_bf16(fx, h0, l0);
            split_bf16(fy, h1, l1);
            int row = warp * 8 + i;
            __nv_bfloat162 ph; ph.x = h0; ph.y = h1;
            __nv_bfloat162 pl; pl.x = l0; pl.y = l1;
            *(__nv_bfloat162*)(Ahi + row * NLDA + c) = ph;
            *(__nv_bfloat162*)(Alo + row * NLDA + c) = pl;
        }

        // ===== B chunk copy, vectorized (2 uint4 per thread per array) =====
        for (int idx = tid; idx < 512; idx += 256) {
            int n = idx >> 3;
            int k8 = (idx & 7) * 8;
            *(uint4*)(Bhi + n * NLDA + k8) = *(const uint4*)(Wh + n * K_TOT + r * 64 + k8);
            *(uint4*)(Blo + n * NLDA + k8) = *(const uint4*)(Wl + n * K_TOT + r * 64 + k8);
        }
        __syncthreads();   // tiles ready

        // ===== 3-pass MMA via ldmatrix =====
        #pragma unroll
        for (int ks = 0; ks < 4; ks++) {
            uint32_t kb = ks * 32;
            uint32_t aH0[4], aH1[4], aL0[4], aL1[4], bH[4], bL[4];
            ldsm4(aH0, aHiAddr + kb);
            ldsm4(aH1, aHiAddr + 16 * (NLDA * 2) + kb);
            ldsm4(aL0, aLoAddr + kb);
            ldsm4(aL1, aLoAddr + 16 * (NLDA * 2) + kb);
            ldsm4(bH, bHiAddr + kb);
            ldsm4(bL, bLoAddr + kb);
            mma16816(C[0], aH0, bH + 0); mma16816(C[1], aH0, bH + 2);
            mma16816(C[2], aH1, bH + 0); mma16816(C[3], aH1, bH + 2);
            mma16816(C[0], aL0, bH + 0); mma16816(C[1], aL0, bH + 2);
            mma16816(C[2], aL1, bH + 0); mma16816(C[3], aL1, bH + 2);
            mma16816(C[0], aH0, bL + 0); mma16816(C[1], aH0, bL + 2);
            mma16816(C[2], aH1, bL + 0); mma16816(C[3], aH1, bL + 2);
        }
    }

    // ===== epilogue =====
    int dorelu = (phase == 0);
    #pragma unroll
    for (int mt = 0; mt < 2; mt++) {
        int r0 = rb + wr + mt * 16 + g;
        int r1 = r0 + 8;
        #pragma unroll
        for (int nt = 0; nt < 2; nt++) {
            int gc = wc + nt * 8 + 2 * t;
            float b0 = bias[gc], b1 = bias[gc + 1];
            float c00 = C[mt * 2 + nt][0] + b0, c01 = C[mt * 2 + nt][1] + b1;
            float c10 = C[mt * 2 + nt][2] + b0, c11 = C[mt * 2 + nt][3] + b1;
            if (dorelu) {
                c00 = fmaxf(c00, 0.f); c01 = fmaxf(c01, 0.f);
                c10 = fmaxf(c10, 0.f); c11 = fmaxf(c11, 0.f);
            }
            if (r0 < N_NODES)
                *(float2*)(OP + (size_t)r0 * 64 + gc) = make_float2(c00, c01);
            if (r1 < N_NODES)
                *(float2*)(OP + (size_t)r1 * 64 + gc) = make_float2(c10, c11);
        }
    }
}

// ---------------- launch ----------------
extern "C" void kernel_launch(void* const* d_in, const int* in_sizes, int n_in,
                              void* d_out, int out_size) {
    const int* feat = (const int*)d_in[0];
    const int* src = (const int*)d_in[1];
    const int* dst = (const int*)d_in[2];
    const int* etype = (const int*)d_in[3];
    const float* norm = (const float*)d_in[4];
    const float* emb = (const float*)d_in[5];
    const float* smw = (const float*)d_in[6];
    const float* smb = (const float*)d_in[7];
    const float* V1 = (const float*)d_in[8];
    const float* c1 = (const float*)d_in[9];
    const float* b1 = (const float*)d_in[10];
    const float* V2 = (const float*)d_in[11];
    const float* c2 = (const float*)d_in[12];
    const float* b2 = (const float*)d_in[13];
    float* out = (float*)d_out;

    const int smemSM = (128 * NLDA * 2 + 64 * NLDA * 2) * 2 + 128 * 8 * 4;
    const int smemFU = 64 * NLDA * 2 * 4 + 128 * ALDA * 4;   // 36864 + 32768 = 69632
    static int attr_done = 0;
    if (!attr_done) {
        cudaFuncSetAttribute(k_front, cudaFuncAttributeMaxDynamicSharedMemorySize, smemSM);
        cudaFuncSetAttribute(k_fused, cudaFuncAttributeMaxDynamicSharedMemorySize, smemFU);
        attr_done = 1;
    }

    k_front<<<NB_SM + NB_PREPW + NB_HIST, 256, smemSM>>>(feat, emb, smw, smb,
                                                         V1, c1, V2, c2, dst, etype);
    k_scan<<<SCAN_NB, 1024>>>();
    k_scatter<<<NB_HIST, 256>>>(src, dst, etype, norm);
    k_fused<<<NB_FU, 256, smemFU>>>(0, b1, nullptr);      // ncu capture slot
    k_fused<<<NB_FU, 256, smemFU>>>(1, b2, out);
}

// round 11
// speedup vs baseline: 2.1562x; 1.0340x over previous
#include <cuda_runtime.h>
#include <cuda_bf16.h>
#include <stdint.h>

#define N_NODES 100000
#define N_EDGES 1600000
#define NUM_RELS 8
#define H_DIM 64
#define K_TOT 512
#define NSEG (N_NODES * NUM_RELS)          // 800000
#define NLDA 72                            // bf16 elems; 144B row stride (16B aligned)
#define ALDA 64                            // Aacc fp32 leading dim (256B rows)
#define NB_SM 782
#define NB_PREPW 256
#define NB_HIST 6250
#define SCAN_NB 782
#define NB_FU 1563                         // ceil(N_NODES/64)

// ---------------- scratch ----------------
__device__ float g_x[(size_t)N_NODES * H_DIM];
__device__ float g_h[(size_t)N_NODES * H_DIM];
__device__ int   g_cnt[SCAN_NB * 1024];     // zero-init; re-zeroed by scan each run
__device__ int   g_rowptr[NSEG + 1];
__device__ int   g_wp[NSEG];
__device__ unsigned long long g_flags[SCAN_NB];  // zero-init; re-zeroed by scatter
__device__ int2  g_emeta[N_EDGES];          // {src | (dst&7)<<20, norm-bits}
__device__ __align__(16) __nv_bfloat16 g_Wth[2 * H_DIM * K_TOT];   // [layer][o*512 + r*64+k]
__device__ __align__(16) __nv_bfloat16 g_Wtl[2 * H_DIM * K_TOT];

// ---------------- helpers ----------------
__device__ __forceinline__ void mma16816(float* c, const uint32_t* a, const uint32_t* b) {
    asm volatile(
        "mma.sync.aligned.m16n8k16.row.col.f32.bf16.bf16.f32 "
        "{%0,%1,%2,%3}, {%4,%5,%6,%7}, {%8,%9}, {%0,%1,%2,%3};\n"
        : "+f"(c[0]), "+f"(c[1]), "+f"(c[2]), "+f"(c[3])
        : "r"(a[0]), "r"(a[1]), "r"(a[2]), "r"(a[3]), "r"(b[0]), "r"(b[1]));
}

__device__ __forceinline__ void ldsm4(uint32_t* r, uint32_t addr) {
    asm volatile("ldmatrix.sync.aligned.m8n8.x4.shared.b16 {%0,%1,%2,%3}, [%4];"
        : "=r"(r[0]), "=r"(r[1]), "=r"(r[2]), "=r"(r[3]) : "r"(addr));
}

// predicated 128-bit smem store: fires only when cond != 0 (no BSSY/branch)
__device__ __forceinline__ void sts128_pred(uint32_t addr, float4 v, int cond) {
    asm volatile(
        "{\n\t.reg .pred p;\n\t"
        "setp.ne.s32 p, %5, 0;\n\t"
        "@p st.shared.v4.f32 [%0], {%1,%2,%3,%4};\n\t}"
        :: "r"(addr), "f"(v.x), "f"(v.y), "f"(v.z), "f"(v.w), "r"(cond) : "memory");
}

__device__ __forceinline__ void split_bf16(float v, __nv_bfloat16& hi, __nv_bfloat16& lo) {
    hi = __float2bfloat16(v);
    lo = __float2bfloat16(v - __bfloat162float(hi));
}

// ---------------- size matcher body (256 threads/block) ----------------
__device__ void sm_body(int bid, const int* __restrict__ feat, const float* __restrict__ emb,
                        const float* __restrict__ smw, const float* __restrict__ smb,
                        char* smraw) {
    __nv_bfloat16* Ahi = (__nv_bfloat16*)smraw;
    __nv_bfloat16* Alo = Ahi + 128 * NLDA;
    __nv_bfloat16* Bhi = Alo + 128 * NLDA;
    __nv_bfloat16* Blo = Bhi + 64 * NLDA;
    int* sfeat = (int*)(Blo + 64 * NLDA);

    int tid = threadIdx.x;
    int rb = bid * 128;

    for (int idx = tid; idx < 128 * 8; idx += 256) {
        int r = idx >> 3, j = idx & 7;
        sfeat[idx] = (rb + r < N_NODES) ? feat[(size_t)(rb + r) * 8 + j] : 0;
    }

    int lane = tid & 31, warp = tid >> 5;
    int wr = (warp >> 2) * 64;
    int wc = (warp & 3) * 16;
    int g = lane >> 2, t = lane & 3;

    float C[8][4];
    #pragma unroll
    for (int i = 0; i < 8; i++)
        #pragma unroll
        for (int j = 0; j < 4; j++) C[i][j] = 0.f;

    for (int kc = 0; kc < 4; kc++) {
        __syncthreads();
        for (int idx = tid; idx < 128 * 64; idx += 256) {
            int r = idx >> 6, k = idx & 63;
            float v = 0.f;
            if (rb + r < N_NODES) {
                int fid = sfeat[r * 8 + kc * 2 + (k >> 5)];
                v = emb[(size_t)fid * 32 + (k & 31)];
            }
            __nv_bfloat16 h, l; split_bf16(v, h, l);
            Ahi[r * NLDA + k] = h; Alo[r * NLDA + k] = l;
        }
        for (int idx = tid; idx < 64 * 64; idx += 256) {
            int n = idx >> 6, k = idx & 63;
            float v = smw[n * 256 + kc * 64 + k];
            __nv_bfloat16 h, l; split_bf16(v, h, l);
            Bhi[n * NLDA + k] = h; Blo[n * NLDA + k] = l;
        }
        __syncthreads();

        #pragma unroll
        for (int ks = 0; ks < 4; ks++) {
            int k0 = ks * 16;
            #pragma unroll
            for (int p = 0; p < 3; p++) {
                const __nv_bfloat16* As = (p == 1) ? Alo : Ahi;
                const __nv_bfloat16* Bs = (p == 2) ? Blo : Bhi;
                uint32_t a[4][4], b[2][2];
                #pragma unroll
                for (int mt = 0; mt < 4; mt++) {
                    int r0 = wr + mt * 16;
                    a[mt][0] = *(const uint32_t*)(As + (r0 + g) * NLDA + k0 + 2 * t);
                    a[mt][1] = *(const uint32_t*)(As + (r0 + g + 8) * NLDA + k0 + 2 * t);
                    a[mt][2] = *(const uint32_t*)(As + (r0 + g) * NLDA + k0 + 8 + 2 * t);
                    a[mt][3] = *(const uint32_t*)(As + (r0 + g + 8) * NLDA + k0 + 8 + 2 * t);
                }
                #pragma unroll
                for (int nt = 0; nt < 2; nt++) {
                    int c0 = wc + nt * 8 + g;
                    b[nt][0] = *(const uint32_t*)(Bs + c0 * NLDA + k0 + 2 * t);
                    b[nt][1] = *(const uint32_t*)(Bs + c0 * NLDA + k0 + 8 + 2 * t);
                }
                #pragma unroll
                for (int mt = 0; mt < 4; mt++)
                    #pragma unroll
                    for (int nt = 0; nt < 2; nt++)
                        mma16816(C[mt * 2 + nt], a[mt], b[nt]);
            }
        }
    }

    #pragma unroll
    for (int mt = 0; mt < 4; mt++) {
        int r0 = rb + wr + mt * 16 + g;
        int r1 = r0 + 8;
        #pragma unroll
        for (int nt = 0; nt < 2; nt++) {
            int gc = wc + nt * 8 + 2 * t;
            float b0 = smb[gc], b1 = smb[gc + 1];
            if (r0 < N_NODES)
                *(float2*)(g_x + (size_t)r0 * 64 + gc) =
                    make_float2(C[mt * 2 + nt][0] + b0, C[mt * 2 + nt][1] + b1);
            if (r1 < N_NODES)
                *(float2*)(g_x + (size_t)r1 * 64 + gc) =
                    make_float2(C[mt * 2 + nt][2] + b0, C[mt * 2 + nt][3] + b1);
        }
    }
}

// ---------------- front kernel: sm + prepw + hist ----------------
__global__ void k_front(const int* __restrict__ feat, const float* __restrict__ emb,
                        const float* __restrict__ smw, const float* __restrict__ smb,
                        const float* __restrict__ V1, const float* __restrict__ c1,
                        const float* __restrict__ V2, const float* __restrict__ c2,
                        const int* __restrict__ dst, const int* __restrict__ etype) {
    extern __shared__ char smraw[];
    int bid = blockIdx.x;
    if (bid < NB_SM) {
        sm_body(bid, feat, emb, smw, smb, smraw);
    } else if (bid < NB_SM + NB_PREPW) {
        int t = (bid - NB_SM) * 256 + threadIdx.x;
        int sel = t >= H_DIM * K_TOT;
        int u = t & (H_DIM * K_TOT - 1);
        int o = u >> 9;
        int c = u & 511;
        int r = c >> 6, k = c & 63;
        const float* V = sel ? V2 : V1;
        const float* cp = sel ? c2 : c1;
        float s = 0.f;
        #pragma unroll
        for (int b = 0; b < 8; b++)
            s += cp[r * 8 + b] * V[(b * 64 + k) * 64 + o];
        __nv_bfloat16 hi = __float2bfloat16(s);
        __nv_bfloat16 lo = __float2bfloat16(s - __bfloat162float(hi));
        g_Wth[t] = hi;
        g_Wtl[t] = lo;
    } else {
        int e = (bid - NB_SM - NB_PREPW) * 256 + threadIdx.x;
        if (e < N_EDGES)
            atomicAdd(&g_cnt[etype[e] * N_NODES + dst[e]], 1);
    }
}

// ---------------- single-kernel scan (decoupled lookback) ----------------
__global__ __launch_bounds__(1024) void k_scan() {
    __shared__ int wsum[32];
    __shared__ int s_excl;
    int tid = threadIdx.x, b = blockIdx.x;
    int i = b * 1024 + tid;
    int v = (i < NSEG) ? g_cnt[i] : 0;
    int lane = tid & 31, wid = tid >> 5;
    int s = v;
    #pragma unroll
    for (int d = 1; d < 32; d <<= 1) {
        int t = __shfl_up_sync(0xFFFFFFFFu, s, d);
        if (lane >= d) s += t;
    }
    if (lane == 31) wsum[wid] = s;
    __syncthreads();
    if (wid == 0) {
        int ws = wsum[lane];
        #pragma unroll
        for (int d = 1; d < 32; d <<= 1) {
            int t = __shfl_up_sync(0xFFFFFFFFu, ws, d);
            if (lane >= d) ws += t;
        }
        wsum[lane] = ws;
    }
    __syncthreads();
    int incl = s + ((wid > 0) ? wsum[wid - 1] : 0);
    int total = wsum[31];

    if (tid == 0) {
        unsigned long long f =
            ((unsigned long long)((b == 0) ? 2u : 1u) << 32) | (unsigned)total;
        atomicExch(&g_flags[b], f);
        if (b == 0) s_excl = 0;
    }
    if (b > 0 && wid == 0) {
        int running = 0;
        int p = b - 1;
        while (true) {
            int idx = p - lane;
            unsigned long long f = (idx >= 0) ? atomicOr(&g_flags[idx], 0ULL)
                                              : (2ULL << 32);
            unsigned st = (unsigned)(f >> 32);
            if (__ballot_sync(0xFFFFFFFFu, st == 0)) continue;
            unsigned b2 = __ballot_sync(0xFFFFFFFFu, st == 2);
            int val = (int)(unsigned)f;
            if (b2) {
                int k = __ffs(b2) - 1;
                int contrib = (lane <= k) ? val : 0;
                #pragma unroll
                for (int off = 16; off > 0; off >>= 1)
                    contrib += __shfl_xor_sync(0xFFFFFFFFu, contrib, off);
                running += contrib;
                break;
            } else {
                int contrib = val;
                #pragma unroll
                for (int off = 16; off > 0; off >>= 1)
                    contrib += __shfl_xor_sync(0xFFFFFFFFu, contrib, off);
                running += contrib;
                p -= 32;
            }
        }
        if (lane == 0) {
            s_excl = running;
            unsigned long long f = (2ULL << 32) | (unsigned)(running + total);
            atomicExch(&g_flags[b], f);
        }
    }
    __syncthreads();
    int rp = s_excl + incl - v;
    if (i < NSEG) {
        g_rowptr[i] = rp;
        g_wp[i] = rp;
        g_cnt[i] = 0;
    }
    if (i == NSEG - 1) g_rowptr[NSEG] = rp + v;
}

// ---------------- scatter (packs row = dst&7; re-zeroes g_flags) ----------------
__global__ void k_scatter(const int* __restrict__ src, const int* __restrict__ dst,
                          const int* __restrict__ etype, const float* __restrict__ norm) {
    int gid = blockIdx.x * blockDim.x + threadIdx.x;
    if (gid < SCAN_NB) g_flags[gid] = 0ULL;
    if (gid >= N_EDGES) return;
    int d = dst[gid];
    int seg = etype[gid] * N_NODES + d;
    int p = atomicAdd(&g_wp[seg], 1);
    g_emeta[p] = make_int2(src[gid] | ((d & 7) << 20), __float_as_int(norm[gid]));
}

// ---------------- fused layer v7: hoisted bounds + pipelined meta ------------------
__global__ __launch_bounds__(256, 3)
void k_fused(int phase, const float* __restrict__ bias, float* __restrict__ dout) {
    const float* __restrict__ X = phase ? g_h : g_x;
    float* __restrict__ OP = phase ? dout : g_h;
    const __nv_bfloat16* __restrict__ Wh = g_Wth + phase * H_DIM * K_TOT;
    const __nv_bfloat16* __restrict__ Wl = g_Wtl + phase * H_DIM * K_TOT;

    extern __shared__ char smraw[];
    __nv_bfloat16* Ahi = (__nv_bfloat16*)smraw;         // 64*72  (9216 B)
    __nv_bfloat16* Alo = Ahi + 64 * NLDA;               // 9216 B
    __nv_bfloat16* Bhi = Alo + 64 * NLDA;               // 9216 B
    __nv_bfloat16* Blo = Bhi + 64 * NLDA;               // 9216 B
    float* Aacc = (float*)(Blo + 64 * NLDA);            // 128 rows * 64 fp32 (32768 B)

    int tid = threadIdx.x;
    int rb = blockIdx.x * 64;
    int lane = tid & 31, warp = tid >> 5;       // 8 warps
    int c = lane * 2;
    int half = lane >> 4;
    int col4 = (lane & 15) * 4;

    int wr = (warp >> 2) * 32;                  // 0 or 32
    int wc = (warp & 3) * 16;                   // 0,16,32,48
    int g = lane >> 2, t = lane & 3;

    // ---- hoist all segment bounds: lane<16 -> relation lane>>1, bound lane&1 ----
    int bb = 0;
    {
        int nidx = min(rb + warp * 8 + ((lane & 1) << 3), N_NODES);
        if (lane < 16) bb = g_rowptr[(lane >> 1) * N_NODES + nidx];
    }

    // ldmatrix per-lane addresses (mapping validated in R7)
    int rowA = (lane & 7) + ((lane >> 3) & 1) * 8;
    int colA = ((lane >> 4) & 1) * 8;
    int rowB = (lane & 7) + ((lane >> 4) & 1) * 8;
    int colB = ((lane >> 3) & 1) * 8;
    uint32_t aHiAddr = (uint32_t)__cvta_generic_to_shared(Ahi) + (wr + rowA) * (NLDA * 2) + colA * 2;
    uint32_t aLoAddr = (uint32_t)__cvta_generic_to_shared(Alo) + (wr + rowA) * (NLDA * 2) + colA * 2;
    uint32_t bHiAddr = (uint32_t)__cvta_generic_to_shared(Bhi) + (wc + rowB) * (NLDA * 2) + colB * 2;
    uint32_t bLoAddr = (uint32_t)__cvta_generic_to_shared(Blo) + (wc + rowB) * (NLDA * 2) + colB * 2;

    float* AaccW = Aacc + (warp * 16) * ALDA;       // 16-row slab: bank0 rows 0-7, bank1 rows 8-15
    float* abase = AaccW + (half * 8) * ALDA + col4;
    uint32_t abaseAddr = (uint32_t)__cvta_generic_to_shared(abase);

    float C[4][4];
    #pragma unroll
    for (int i = 0; i < 4; i++)
        #pragma unroll
        for (int j = 0; j < 4; j++) C[i][j] = 0.f;

    for (int r = 0; r < NUM_RELS; r++) {
        // ===== zero own bank rows =====
        #pragma unroll
        for (int i = 0; i < 8; i++)
            *(float4*)(abase + i * ALDA) = make_float4(0.f, 0.f, 0.f, 0.f);

        // ===== warp edge range from hoisted registers (no LDG) =====
        int wbeg = __shfl_sync(0xFFFFFFFFu, bb, 2 * r);
        int wend = __shfl_sync(0xFFFFFFFFu, bb, 2 * r + 1);
        int cnt = wend - wbeg;

        // ===== aggregation: run-flush with software-pipelined meta =====
        {
            float4 acc = make_float4(0.f, 0.f, 0.f, 0.f);
            int cur = 0;
            int jmax = (cnt + 1) >> 1;         // edges for this half
            int eBase = wbeg + half;
            int eSafe = max(wend - 1, 0);
            int2 m0 = g_emeta[min(eBase, eSafe)];
            int2 m1 = g_emeta[min(eBase + 2, eSafe)];
            for (int j = 0; j < jmax; j += 2) {
                int e0 = eBase + 2 * j;
                int e1 = e0 + 2;
                int2 c0 = m0, c1 = m1;
                m0 = g_emeta[min(e1 + 2, eSafe)];      // prefetch next pair
                m1 = g_emeta[min(e1 + 4, eSafe)];
                float nn0 = (e0 < wend) ? __int_as_float(c0.y) : 0.f;
                float nn1 = (e1 < wend) ? __int_as_float(c1.y) : 0.f;
                float4 v0 = *(const float4*)(X + (size_t)(c0.x & 0xFFFFF) * 64 + col4);
                float4 v1 = *(const float4*)(X + (size_t)(c1.x & 0xFFFFF) * 64 + col4);
                int rw0 = (c0.x >> 20) & 7;
                int rw1 = (c1.x >> 20) & 7;

                int fl0 = rw0 - cur;                   // >0 on row change (sorted)
                sts128_pred(abaseAddr + cur * 256, acc, fl0);
                acc.x = fl0 ? 0.f : acc.x; acc.y = fl0 ? 0.f : acc.y;
                acc.z = fl0 ? 0.f : acc.z; acc.w = fl0 ? 0.f : acc.w;
                cur = rw0;
                acc.x = fmaf(nn0, v0.x, acc.x); acc.y = fmaf(nn0, v0.y, acc.y);
                acc.z = fmaf(nn0, v0.z, acc.z); acc.w = fmaf(nn0, v0.w, acc.w);

                int fl1 = rw1 - cur;
                sts128_pred(abaseAddr + cur * 256, acc, fl1);
                acc.x = fl1 ? 0.f : acc.x; acc.y = fl1 ? 0.f : acc.y;
                acc.z = fl1 ? 0.f : acc.z; acc.w = fl1 ? 0.f : acc.w;
                cur = rw1;
                acc.x = fmaf(nn1, v1.x, acc.x); acc.y = fmaf(nn1, v1.y, acc.y);
                acc.z = fmaf(nn1, v1.z, acc.z); acc.w = fmaf(nn1, v1.w, acc.w);
            }
            // final flush (cnt==0 -> stores zeros over pre-zeroed row 0: harmless)
            *(float4*)(abase + cur * ALDA) = acc;
        }

        __syncthreads();   // prior chunk's fragment reads + this chunk's Aacc ready

        // ===== convert: sum banks -> bf16 hi/lo tiles (own 8 rows) =====
        #pragma unroll
        for (int i = 0; i < 8; i++) {
            float2 a0 = *(float2*)(AaccW + i * ALDA + c);
            float2 a1 = *(float2*)(AaccW + (8 + i) * ALDA + c);
            float fx = a0.x + a1.x, fy = a0.y + a1.y;
            __nv_bfloat16 h0, l0, h1, l1;
            split_bf16(fx, h0, l0);
            split_bf16(fy, h1, l1);
            int row = warp * 8 + i;
            __nv_bfloat162 ph; ph.x = h0; ph.y = h1;
            __nv_bfloat162 pl; pl.x = l0; pl.y = l1;
            *(__nv_bfloat162*)(Ahi + row * NLDA + c) = ph;
            *(__nv_bfloat162*)(Alo + row * NLDA + c) = pl;
        }

        // ===== B chunk copy, vectorized (2 uint4 per thread per array) =====
        for (int idx = tid; idx < 512; idx += 256) {
            int n = idx >> 3;
            int k8 = (idx & 7) * 8;
            *(uint4*)(Bhi + n * NLDA + k8) = *(const uint4*)(Wh + n * K_TOT + r * 64 + k8);
            *(uint4*)(Blo + n * NLDA + k8) = *(const uint4*)(Wl + n * K_TOT + r * 64 + k8);
        }
        __syncthreads();   // tiles ready

        // ===== 3-pass MMA via ldmatrix =====
        #pragma unroll
        for (int ks = 0; ks < 4; ks++) {
            uint32_t kb = ks * 32;
            uint32_t aH0[4], aH1[4], aL0[4], aL1[4], bH[4], bL[4];
            ldsm4(aH0, aHiAddr + kb);
            ldsm4(aH1, aHiAddr + 16 * (NLDA * 2) + kb);
            ldsm4(aL0, aLoAddr + kb);
            ldsm4(aL1, aLoAddr + 16 * (NLDA * 2) + kb);
            ldsm4(bH, bHiAddr + kb);
            ldsm4(bL, bLoAddr + kb);
            mma16816(C[0], aH0, bH + 0); mma16816(C[1], aH0, bH + 2);
            mma16816(C[2], aH1, bH + 0); mma16816(C[3], aH1, bH + 2);
            mma16816(C[0], aL0, bH + 0); mma16816(C[1], aL0, bH + 2);
            mma16816(C[2], aL1, bH + 0); mma16816(C[3], aL1, bH + 2);
            mma16816(C[0], aH0, bL + 0); mma16816(C[1], aH0, bL + 2);
            mma16816(C[2], aH1, bL + 0); mma16816(C[3], aH1, bL + 2);
        }
    }

    // ===== epilogue =====
    int dorelu = (phase == 0);
    #pragma unroll
    for (int mt = 0; mt < 2; mt++) {
        int r0 = rb + wr + mt * 16 + g;
        int r1 = r0 + 8;
        #pragma unroll
        for (int nt = 0; nt < 2; nt++) {
            int gc = wc + nt * 8 + 2 * t;
            float b0 = bias[gc], b1 = bias[gc + 1];
            float c00 = C[mt * 2 + nt][0] + b0, c01 = C[mt * 2 + nt][1] + b1;
            float c10 = C[mt * 2 + nt][2] + b0, c11 = C[mt * 2 + nt][3] + b1;
            if (dorelu) {
                c00 = fmaxf(c00, 0.f); c01 = fmaxf(c01, 0.f);
                c10 = fmaxf(c10, 0.f); c11 = fmaxf(c11, 0.f);
            }
            if (r0 < N_NODES)
                *(float2*)(OP + (size_t)r0 * 64 + gc) = make_float2(c00, c01);
            if (r1 < N_NODES)
                *(float2*)(OP + (size_t)r1 * 64 + gc) = make_float2(c10, c11);
        }
    }
}

// ---------------- launch ----------------
extern "C" void kernel_launch(void* const* d_in, const int* in_sizes, int n_in,
                              void* d_out, int out_size) {
    const int* feat = (const int*)d_in[0];
    const int* src = (const int*)d_in[1];
    const int* dst = (const int*)d_in[2];
    const int* etype = (const int*)d_in[3];
    const float* norm = (const float*)d_in[4];
    const float* emb = (const float*)d_in[5];
    const float* smw = (const float*)d_in[6];
    const float* smb = (const float*)d_in[7];
    const float* V1 = (const float*)d_in[8];
    const float* c1 = (const float*)d_in[9];
    const float* b1 = (const float*)d_in[10];
    const float* V2 = (const float*)d_in[11];
    const float* c2 = (const float*)d_in[12];
    const float* b2 = (const float*)d_in[13];
    float* out = (float*)d_out;

    const int smemSM = (128 * NLDA * 2 + 64 * NLDA * 2) * 2 + 128 * 8 * 4;
    const int smemFU = 64 * NLDA * 2 * 4 + 128 * ALDA * 4;   // 36864 + 32768 = 69632
    static int attr_done = 0;
    if (!attr_done) {
        cudaFuncSetAttribute(k_front, cudaFuncAttributeMaxDynamicSharedMemorySize, smemSM);
        cudaFuncSetAttribute(k_fused, cudaFuncAttributeMaxDynamicSharedMemorySize, smemFU);
        attr_done = 1;
    }

    k_front<<<NB_SM + NB_PREPW + NB_HIST, 256, smemSM>>>(feat, emb, smw, smb,
                                                         V1, c1, V2, c2, dst, etype);
    k_scan<<<SCAN_NB, 1024>>>();
    k_scatter<<<NB_HIST, 256>>>(src, dst, etype, norm);
    k_fused<<<NB_FU, 256, smemFU>>>(0, b1, nullptr);      // ncu capture slot
    k_fused<<<NB_FU, 256, smemFU>>>(1, b2, out);
}

// round 12
// speedup vs baseline: 2.2381x; 1.0380x over previous
#include <cuda_runtime.h>
#include <cuda_bf16.h>
#include <stdint.h>

#define N_NODES 100000
#define N_EDGES 1600000
#define NUM_RELS 8
#define H_DIM 64
#define K_TOT 512
#define NSEG (N_NODES * NUM_RELS)          // 800000
#define NLDA 72                            // bf16 elems; 144B row stride (16B aligned)
#define ALDA 68                            // Aacc fp32 leading dim (272B rows, conflict-free)
#define NB_SM 782
#define NB_PREPW 256
#define NB_HIST 6250
#define SCAN_NB 782
#define NB_FU 1563                         // ceil(N_NODES/64)

// ---------------- scratch ----------------
__device__ float g_x[(size_t)N_NODES * H_DIM];
__device__ float g_h[(size_t)N_NODES * H_DIM];
__device__ int   g_cnt[SCAN_NB * 1024];     // zero-init; re-zeroed by scan each run
__device__ int   g_rowptr[NSEG + 1];
__device__ int   g_wp[NSEG];
__device__ unsigned long long g_flags[SCAN_NB];  // zero-init; re-zeroed by scatter
__device__ int2  g_emeta[N_EDGES];          // {src | (dst&7)<<20, norm-bits}
__device__ __align__(16) __nv_bfloat16 g_Wth[2 * H_DIM * K_TOT];   // [layer][o*512 + r*64+k]
__device__ __align__(16) __nv_bfloat16 g_Wtl[2 * H_DIM * K_TOT];

// ---------------- helpers ----------------
__device__ __forceinline__ void mma16816(float* c, const uint32_t* a, const uint32_t* b) {
    asm volatile(
        "mma.sync.aligned.m16n8k16.row.col.f32.bf16.bf16.f32 "
        "{%0,%1,%2,%3}, {%4,%5,%6,%7}, {%8,%9}, {%0,%1,%2,%3};\n"
        : "+f"(c[0]), "+f"(c[1]), "+f"(c[2]), "+f"(c[3])
        : "r"(a[0]), "r"(a[1]), "r"(a[2]), "r"(a[3]), "r"(b[0]), "r"(b[1]));
}

__device__ __forceinline__ void ldsm4(uint32_t* r, uint32_t addr) {
    asm volatile("ldmatrix.sync.aligned.m8n8.x4.shared.b16 {%0,%1,%2,%3}, [%4];"
        : "=r"(r[0]), "=r"(r[1]), "=r"(r[2]), "=r"(r[3]) : "r"(addr));
}

// predicated 128-bit smem store: fires only when cond != 0 (no BSSY/branch)
__device__ __forceinline__ void sts128_pred(uint32_t addr, float4 v, int cond) {
    asm volatile(
        "{\n\t.reg .pred p;\n\t"
        "setp.ne.s32 p, %5, 0;\n\t"
        "@p st.shared.v4.f32 [%0], {%1,%2,%3,%4};\n\t}"
        :: "r"(addr), "f"(v.x), "f"(v.y), "f"(v.z), "f"(v.w), "r"(cond) : "memory");
}

__device__ __forceinline__ void split_bf16(float v, __nv_bfloat16& hi, __nv_bfloat16& lo) {
    hi = __float2bfloat16(v);
    lo = __float2bfloat16(v - __bfloat162float(hi));
}

__device__ __forceinline__ uint32_t pack_bf2(__nv_bfloat16 a, __nv_bfloat16 b) {
    __nv_bfloat162 p; p.x = a; p.y = b;
    return *(uint32_t*)&p;
}

// ---------------- size matcher body (256 threads/block) ----------------
__device__ void sm_body(int bid, const int* __restrict__ feat, const float* __restrict__ emb,
                        const float* __restrict__ smw, const float* __restrict__ smb,
                        char* smraw) {
    __nv_bfloat16* Ahi = (__nv_bfloat16*)smraw;
    __nv_bfloat16* Alo = Ahi + 128 * NLDA;
    __nv_bfloat16* Bhi = Alo + 128 * NLDA;
    __nv_bfloat16* Blo = Bhi + 64 * NLDA;
    int* sfeat = (int*)(Blo + 64 * NLDA);

    int tid = threadIdx.x;
    int rb = bid * 128;

    for (int idx = tid; idx < 128 * 8; idx += 256) {
        int r = idx >> 3, j = idx & 7;
        sfeat[idx] = (rb + r < N_NODES) ? feat[(size_t)(rb + r) * 8 + j] : 0;
    }

    int lane = tid & 31, warp = tid >> 5;
    int wr = (warp >> 2) * 64;
    int wc = (warp & 3) * 16;
    int g = lane >> 2, t = lane & 3;

    float C[8][4];
    #pragma unroll
    for (int i = 0; i < 8; i++)
        #pragma unroll
        for (int j = 0; j < 4; j++) C[i][j] = 0.f;

    for (int kc = 0; kc < 4; kc++) {
        __syncthreads();
        for (int idx = tid; idx < 128 * 64; idx += 256) {
            int r = idx >> 6, k = idx & 63;
            float v = 0.f;
            if (rb + r < N_NODES) {
                int fid = sfeat[r * 8 + kc * 2 + (k >> 5)];
                v = emb[(size_t)fid * 32 + (k & 31)];
            }
            __nv_bfloat16 h, l; split_bf16(v, h, l);
            Ahi[r * NLDA + k] = h; Alo[r * NLDA + k] = l;
        }
        for (int idx = tid; idx < 64 * 64; idx += 256) {
            int n = idx >> 6, k = idx & 63;
            float v = smw[n * 256 + kc * 64 + k];
            __nv_bfloat16 h, l; split_bf16(v, h, l);
            Bhi[n * NLDA + k] = h; Blo[n * NLDA + k] = l;
        }
        __syncthreads();

        #pragma unroll
        for (int ks = 0; ks < 4; ks++) {
            int k0 = ks * 16;
            #pragma unroll
            for (int p = 0; p < 3; p++) {
                const __nv_bfloat16* As = (p == 1) ? Alo : Ahi;
                const __nv_bfloat16* Bs = (p == 2) ? Blo : Bhi;
                uint32_t a[4][4], b[2][2];
                #pragma unroll
                for (int mt = 0; mt < 4; mt++) {
                    int r0 = wr + mt * 16;
                    a[mt][0] = *(const uint32_t*)(As + (r0 + g) * NLDA + k0 + 2 * t);
                    a[mt][1] = *(const uint32_t*)(As + (r0 + g + 8) * NLDA + k0 + 2 * t);
                    a[mt][2] = *(const uint32_t*)(As + (r0 + g) * NLDA + k0 + 8 + 2 * t);
                    a[mt][3] = *(const uint32_t*)(As + (r0 + g + 8) * NLDA + k0 + 8 + 2 * t);
                }
                #pragma unroll
                for (int nt = 0; nt < 2; nt++) {
                    int c0 = wc + nt * 8 + g;
                    b[nt][0] = *(const uint32_t*)(Bs + c0 * NLDA + k0 + 2 * t);
                    b[nt][1] = *(const uint32_t*)(Bs + c0 * NLDA + k0 + 8 + 2 * t);
                }
                #pragma unroll
                for (int mt = 0; mt < 4; mt++)
                    #pragma unroll
                    for (int nt = 0; nt < 2; nt++)
                        mma16816(C[mt * 2 + nt], a[mt], b[nt]);
            }
        }
    }

    #pragma unroll
    for (int mt = 0; mt < 4; mt++) {
        int r0 = rb + wr + mt * 16 + g;
        int r1 = r0 + 8;
        #pragma unroll
        for (int nt = 0; nt < 2; nt++) {
            int gc = wc + nt * 8 + 2 * t;
            float b0 = smb[gc], b1 = smb[gc + 1];
            if (r0 < N_NODES)
                *(float2*)(g_x + (size_t)r0 * 64 + gc) =
                    make_float2(C[mt * 2 + nt][0] + b0, C[mt * 2 + nt][1] + b1);
            if (r1 < N_NODES)
                *(float2*)(g_x + (size_t)r1 * 64 + gc) =
                    make_float2(C[mt * 2 + nt][2] + b0, C[mt * 2 + nt][3] + b1);
        }
    }
}

// ---------------- front kernel: sm + prepw + hist ----------------
__global__ void k_front(const int* __restrict__ feat, const float* __restrict__ emb,
                        const float* __restrict__ smw, const float* __restrict__ smb,
                        const float* __restrict__ V1, const float* __restrict__ c1,
                        const float* __restrict__ V2, const float* __restrict__ c2,
                        const int* __restrict__ dst, const int* __restrict__ etype) {
    extern __shared__ char smraw[];
    int bid = blockIdx.x;
    if (bid < NB_SM) {
        sm_body(bid, feat, emb, smw, smb, smraw);
    } else if (bid < NB_SM + NB_PREPW) {
        int t = (bid - NB_SM) * 256 + threadIdx.x;
        int sel = t >= H_DIM * K_TOT;
        int u = t & (H_DIM * K_TOT - 1);
        int o = u >> 9;
        int c = u & 511;
        int r = c >> 6, k = c & 63;
        const float* V = sel ? V2 : V1;
        const float* cp = sel ? c2 : c1;
        float s = 0.f;
        #pragma unroll
        for (int b = 0; b < 8; b++)
            s += cp[r * 8 + b] * V[(b * 64 + k) * 64 + o];
        __nv_bfloat16 hi = __float2bfloat16(s);
        __nv_bfloat16 lo = __float2bfloat16(s - __bfloat162float(hi));
        g_Wth[t] = hi;
        g_Wtl[t] = lo;
    } else {
        int e = (bid - NB_SM - NB_PREPW) * 256 + threadIdx.x;
        if (e < N_EDGES)
            atomicAdd(&g_cnt[etype[e] * N_NODES + dst[e]], 1);
    }
}

// ---------------- single-kernel scan (decoupled lookback) ----------------
__global__ __launch_bounds__(1024) void k_scan() {
    __shared__ int wsum[32];
    __shared__ int s_excl;
    int tid = threadIdx.x, b = blockIdx.x;
    int i = b * 1024 + tid;
    int v = (i < NSEG) ? g_cnt[i] : 0;
    int lane = tid & 31, wid = tid >> 5;
    int s = v;
    #pragma unroll
    for (int d = 1; d < 32; d <<= 1) {
        int t = __shfl_up_sync(0xFFFFFFFFu, s, d);
        if (lane >= d) s += t;
    }
    if (lane == 31) wsum[wid] = s;
    __syncthreads();
    if (wid == 0) {
        int ws = wsum[lane];
        #pragma unroll
        for (int d = 1; d < 32; d <<= 1) {
            int t = __shfl_up_sync(0xFFFFFFFFu, ws, d);
            if (lane >= d) ws += t;
        }
        wsum[lane] = ws;
    }
    __syncthreads();
    int incl = s + ((wid > 0) ? wsum[wid - 1] : 0);
    int total = wsum[31];

    if (tid == 0) {
        unsigned long long f =
            ((unsigned long long)((b == 0) ? 2u : 1u) << 32) | (unsigned)total;
        atomicExch(&g_flags[b], f);
        if (b == 0) s_excl = 0;
    }
    if (b > 0 && wid == 0) {
        int running = 0;
        int p = b - 1;
        while (true) {
            int idx = p - lane;
            unsigned long long f = (idx >= 0) ? atomicOr(&g_flags[idx], 0ULL)
                                              : (2ULL << 32);
            unsigned st = (unsigned)(f >> 32);
            if (__ballot_sync(0xFFFFFFFFu, st == 0)) continue;
            unsigned b2 = __ballot_sync(0xFFFFFFFFu, st == 2);
            int val = (int)(unsigned)f;
            if (b2) {
                int k = __ffs(b2) - 1;
                int contrib = (lane <= k) ? val : 0;
                #pragma unroll
                for (int off = 16; off > 0; off >>= 1)
                    contrib += __shfl_xor_sync(0xFFFFFFFFu, contrib, off);
                running += contrib;
                break;
            } else {
                int contrib = val;
                #pragma unroll
                for (int off = 16; off > 0; off >>= 1)
                    contrib += __shfl_xor_sync(0xFFFFFFFFu, contrib, off);
                running += contrib;
                p -= 32;
            }
        }
        if (lane == 0) {
            s_excl = running;
            unsigned long long f = (2ULL << 32) | (unsigned)(running + total);
            atomicExch(&g_flags[b], f);
        }
    }
    __syncthreads();
    int rp = s_excl + incl - v;
    if (i < NSEG) {
        g_rowptr[i] = rp;
        g_wp[i] = rp;
        g_cnt[i] = 0;
    }
    if (i == NSEG - 1) g_rowptr[NSEG] = rp + v;
}

// ---------------- scatter (packs row = dst&7; re-zeroes g_flags) ----------------
__global__ void k_scatter(const int* __restrict__ src, const int* __restrict__ dst,
                          const int* __restrict__ etype, const float* __restrict__ norm) {
    int gid = blockIdx.x * blockDim.x + threadIdx.x;
    if (gid < SCAN_NB) g_flags[gid] = 0ULL;
    if (gid >= N_EDGES) return;
    int d = dst[gid];
    int seg = etype[gid] * N_NODES + d;
    int p = atomicAdd(&g_wp[seg], 1);
    g_emeta[p] = make_int2(src[gid] | ((d & 7) << 20), __float_as_int(norm[gid]));
}

// ---------------- fused layer v8: row×colgroup convert + v7 edge loop --------------
__global__ __launch_bounds__(256, 3)
void k_fused(int phase, const float* __restrict__ bias, float* __restrict__ dout) {
    const float* __restrict__ X = phase ? g_h : g_x;
    float* __restrict__ OP = phase ? dout : g_h;
    const __nv_bfloat16* __restrict__ Wh = g_Wth + phase * H_DIM * K_TOT;
    const __nv_bfloat16* __restrict__ Wl = g_Wtl + phase * H_DIM * K_TOT;

    extern __shared__ char smraw[];
    __nv_bfloat16* Ahi = (__nv_bfloat16*)smraw;         // 64*72  (9216 B)
    __nv_bfloat16* Alo = Ahi + 64 * NLDA;               // 9216 B
    __nv_bfloat16* Bhi = Alo + 64 * NLDA;               // 9216 B
    __nv_bfloat16* Blo = Bhi + 64 * NLDA;               // 9216 B
    float* Aacc = (float*)(Blo + 64 * NLDA);            // 128 rows * 68 fp32 (34816 B)

    int tid = threadIdx.x;
    int rb = blockIdx.x * 64;
    int lane = tid & 31, warp = tid >> 5;       // 8 warps
    int half = lane >> 4;
    int col4 = (lane & 15) * 4;

    int wr = (warp >> 2) * 32;                  // 0 or 32
    int wc = (warp & 3) * 16;                   // 0,16,32,48
    int g = lane >> 2, t = lane & 3;

    // ---- hoist all segment bounds: lane<16 -> relation lane>>1, bound lane&1 ----
    int bb = 0;
    {
        int nidx = min(rb + warp * 8 + ((lane & 1) << 3), N_NODES);
        if (lane < 16) bb = g_rowptr[(lane >> 1) * N_NODES + nidx];
    }

    // ldmatrix per-lane addresses (mapping validated in R7)
    int rowA = (lane & 7) + ((lane >> 3) & 1) * 8;
    int colA = ((lane >> 4) & 1) * 8;
    int rowB = (lane & 7) + ((lane >> 4) & 1) * 8;
    int colB = ((lane >> 3) & 1) * 8;
    uint32_t aHiAddr = (uint32_t)__cvta_generic_to_shared(Ahi) + (wr + rowA) * (NLDA * 2) + colA * 2;
    uint32_t aLoAddr = (uint32_t)__cvta_generic_to_shared(Alo) + (wr + rowA) * (NLDA * 2) + colA * 2;
    uint32_t bHiAddr = (uint32_t)__cvta_generic_to_shared(Bhi) + (wc + rowB) * (NLDA * 2) + colB * 2;
    uint32_t bLoAddr = (uint32_t)__cvta_generic_to_shared(Blo) + (wc + rowB) * (NLDA * 2) + colB * 2;

    float* AaccW = Aacc + (warp * 16) * ALDA;       // 16-row slab: bank0 rows 0-7, bank1 rows 8-15
    float* abase = AaccW + (half * 8) * ALDA + col4;
    uint32_t abaseAddr = (uint32_t)__cvta_generic_to_shared(abase);

    float C[4][4];
    #pragma unroll
    for (int i = 0; i < 4; i++)
        #pragma unroll
        for (int j = 0; j < 4; j++) C[i][j] = 0.f;

    for (int r = 0; r < NUM_RELS; r++) {
        // ===== zero own bank rows =====
        #pragma unroll
        for (int i = 0; i < 8; i++)
            *(float4*)(abase + i * ALDA) = make_float4(0.f, 0.f, 0.f, 0.f);

        // ===== warp edge range from hoisted registers (no LDG) =====
        int wbeg = __shfl_sync(0xFFFFFFFFu, bb, 2 * r);
        int wend = __shfl_sync(0xFFFFFFFFu, bb, 2 * r + 1);
        int cnt = wend - wbeg;

        // ===== aggregation: run-flush with software-pipelined meta =====
        {
            float4 acc = make_float4(0.f, 0.f, 0.f, 0.f);
            int cur = 0;
            int jmax = (cnt + 1) >> 1;         // edges for this half
            int eBase = wbeg + half;
            int eSafe = max(wend - 1, 0);
            int2 m0 = g_emeta[min(eBase, eSafe)];
            int2 m1 = g_emeta[min(eBase + 2, eSafe)];
            for (int j = 0; j < jmax; j += 2) {
                int e0 = eBase + 2 * j;
                int e1 = e0 + 2;
                int2 c0 = m0, c1 = m1;
                m0 = g_emeta[min(e1 + 2, eSafe)];      // prefetch next pair
                m1 = g_emeta[min(e1 + 4, eSafe)];
                float nn0 = (e0 < wend) ? __int_as_float(c0.y) : 0.f;
                float nn1 = (e1 < wend) ? __int_as_float(c1.y) : 0.f;
                float4 v0 = *(const float4*)(X + (size_t)(c0.x & 0xFFFFF) * 64 + col4);
                float4 v1 = *(const float4*)(X + (size_t)(c1.x & 0xFFFFF) * 64 + col4);
                int rw0 = (c0.x >> 20) & 7;
                int rw1 = (c1.x >> 20) & 7;

                int fl0 = rw0 - cur;                   // >0 on row change (sorted)
                sts128_pred(abaseAddr + cur * (ALDA * 4), acc, fl0);
                acc.x = fl0 ? 0.f : acc.x; acc.y = fl0 ? 0.f : acc.y;
                acc.z = fl0 ? 0.f : acc.z; acc.w = fl0 ? 0.f : acc.w;
                cur = rw0;
                acc.x = fmaf(nn0, v0.x, acc.x); acc.y = fmaf(nn0, v0.y, acc.y);
                acc.z = fmaf(nn0, v0.z, acc.z); acc.w = fmaf(nn0, v0.w, acc.w);

                int fl1 = rw1 - cur;
                sts128_pred(abaseAddr + cur * (ALDA * 4), acc, fl1);
                acc.x = fl1 ? 0.f : acc.x; acc.y = fl1 ? 0.f : acc.y;
                acc.z = fl1 ? 0.f : acc.z; acc.w = fl1 ? 0.f : acc.w;
                cur = rw1;
                acc.x = fmaf(nn1, v1.x, acc.x); acc.y = fmaf(nn1, v1.y, acc.y);
                acc.z = fmaf(nn1, v1.z, acc.z); acc.w = fmaf(nn1, v1.w, acc.w);
            }
            // final flush (cnt==0 -> stores zeros over pre-zeroed row 0: harmless)
            *(float4*)(abase + cur * ALDA) = acc;
        }

        __syncthreads();   // prior chunk's fragment reads + this chunk's Aacc ready

        // ===== convert v2: lane = (row l&7, colgroup l>>3); 8 LDS.128 + 4 STS.128 ====
        {
            int crow = lane & 7;
            int ccg = lane >> 3;                        // 0..3, 16 cols each
            const float* pa0 = AaccW + crow * ALDA + ccg * 16;
            const float* pa1 = pa0 + 8 * ALDA;
            uint32_t hb[8], lb[8];
            #pragma unroll
            for (int q = 0; q < 4; q++) {
                float4 u = *(const float4*)(pa0 + q * 4);
                float4 w = *(const float4*)(pa1 + q * 4);
                float f0 = u.x + w.x, f1 = u.y + w.y;
                float f2 = u.z + w.z, f3 = u.w + w.w;
                __nv_bfloat16 h0, l0, h1, l1, h2, l2, h3, l3;
                split_bf16(f0, h0, l0); split_bf16(f1, h1, l1);
                split_bf16(f2, h2, l2); split_bf16(f3, h3, l3);
                hb[q * 2]     = pack_bf2(h0, h1);
                hb[q * 2 + 1] = pack_bf2(h2, h3);
                lb[q * 2]     = pack_bf2(l0, l1);
                lb[q * 2 + 1] = pack_bf2(l2, l3);
            }
            int trow = warp * 8 + crow;
            uint4* dh = (uint4*)(Ahi + trow * NLDA + ccg * 16);
            uint4* dl = (uint4*)(Alo + trow * NLDA + ccg * 16);
            dh[0] = make_uint4(hb[0], hb[1], hb[2], hb[3]);
            dh[1] = make_uint4(hb[4], hb[5], hb[6], hb[7]);
            dl[0] = make_uint4(lb[0], lb[1], lb[2], lb[3]);
            dl[1] = make_uint4(lb[4], lb[5], lb[6], lb[7]);
        }

        // ===== B chunk copy, vectorized (2 uint4 per thread per array) =====
        for (int idx = tid; idx < 512; idx += 256) {
            int n = idx >> 3;
            int k8 = (idx & 7) * 8;
            *(uint4*)(Bhi + n * NLDA + k8) = *(const uint4*)(Wh + n * K_TOT + r * 64 + k8);
            *(uint4*)(Blo + n * NLDA + k8) = *(const uint4*)(Wl + n * K_TOT + r * 64 + k8);
        }
        __syncthreads();   // tiles ready

        // ===== 3-pass MMA via ldmatrix =====
        #pragma unroll
        for (int ks = 0; ks < 4; ks++) {
            uint32_t kb = ks * 32;
            uint32_t aH0[4], aH1[4], aL0[4], aL1[4], bH[4], bL[4];
            ldsm4(aH0, aHiAddr + kb);
            ldsm4(aH1, aHiAddr + 16 * (NLDA * 2) + kb);
            ldsm4(aL0, aLoAddr + kb);
            ldsm4(aL1, aLoAddr + 16 * (NLDA * 2) + kb);
            ldsm4(bH, bHiAddr + kb);
            ldsm4(bL, bLoAddr + kb);
            mma16816(C[0], aH0, bH + 0); mma16816(C[1], aH0, bH + 2);
            mma16816(C[2], aH1, bH + 0); mma16816(C[3], aH1, bH + 2);
            mma16816(C[0], aL0, bH + 0); mma16816(C[1], aL0, bH + 2);
            mma16816(C[2], aL1, bH + 0); mma16816(C[3], aL1, bH + 2);
            mma16816(C[0], aH0, bL + 0); mma16816(C[1], aH0, bL + 2);
            mma16816(C[2], aH1, bL + 0); mma16816(C[3], aH1, bL + 2);
        }
    }

    // ===== epilogue =====
    int dorelu = (phase == 0);
    #pragma unroll
    for (int mt = 0; mt < 2; mt++) {
        int r0 = rb + wr + mt * 16 + g;
        int r1 = r0 + 8;
        #pragma unroll
        for (int nt = 0; nt < 2; nt++) {
            int gc = wc + nt * 8 + 2 * t;
            float b0 = bias[gc], b1 = bias[gc + 1];
            float c00 = C[mt * 2 + nt][0] + b0, c01 = C[mt * 2 + nt][1] + b1;
            float c10 = C[mt * 2 + nt][2] + b0, c11 = C[mt * 2 + nt][3] + b1;
            if (dorelu) {
                c00 = fmaxf(c00, 0.f); c01 = fmaxf(c01, 0.f);
                c10 = fmaxf(c10, 0.f); c11 = fmaxf(c11, 0.f);
            }
            if (r0 < N_NODES)
                *(float2*)(OP + (size_t)r0 * 64 + gc) = make_float2(c00, c01);
            if (r1 < N_NODES)
                *(float2*)(OP + (size_t)r1 * 64 + gc) = make_float2(c10, c11);
        }
    }
}

// ---------------- launch ----------------
extern "C" void kernel_launch(void* const* d_in, const int* in_sizes, int n_in,
                              void* d_out, int out_size) {
    const int* feat = (const int*)d_in[0];
    const int* src = (const int*)d_in[1];
    const int* dst = (const int*)d_in[2];
    const int* etype = (const int*)d_in[3];
    const float* norm = (const float*)d_in[4];
    const float* emb = (const float*)d_in[5];
    const float* smw = (const float*)d_in[6];
    const float* smb = (const float*)d_in[7];
    const float* V1 = (const float*)d_in[8];
    const float* c1 = (const float*)d_in[9];
    const float* b1 = (const float*)d_in[10];
    const float* V2 = (const float*)d_in[11];
    const float* c2 = (const float*)d_in[12];
    const float* b2 = (const float*)d_in[13];
    float* out = (float*)d_out;

    const int smemSM = (128 * NLDA * 2 + 64 * NLDA * 2) * 2 + 128 * 8 * 4;
    const int smemFU = 64 * NLDA * 2 * 4 + 128 * ALDA * 4;   // 36864 + 34816 = 71680
    static int attr_done = 0;
    if (!attr_done) {
        cudaFuncSetAttribute(k_front, cudaFuncAttributeMaxDynamicSharedMemorySize, smemSM);
        cudaFuncSetAttribute(k_fused, cudaFuncAttributeMaxDynamicSharedMemorySize, smemFU);
        attr_done = 1;
    }

    k_front<<<NB_SM + NB_PREPW + NB_HIST, 256, smemSM>>>(feat, emb, smw, smb,
                                                         V1, c1, V2, c2, dst, etype);
    k_scan<<<SCAN_NB, 1024>>>();
    k_scatter<<<NB_HIST, 256>>>(src, dst, etype, norm);
    k_fused<<<NB_FU, 256, smemFU>>>(0, b1, nullptr);      // ncu capture slot
    k_fused<<<NB_FU, 256, smemFU>>>(1, b2, out);
}

// round 13
// speedup vs baseline: 2.4791x; 1.1077x over previous
#include <cuda_runtime.h>
#include <cuda_bf16.h>
#include <stdint.h>

#define N_NODES 100000
#define N_EDGES 1600000
#define NUM_RELS 8
#define H_DIM 64
#define K_TOT 512
#define NSEG (N_NODES * NUM_RELS)          // 800000
#define NLDA 72                            // bf16 elems; 144B row stride (16B aligned)
#define ALDA 68                            // Aacc fp32 leading dim (272B rows, conflict-free)
#define NB_SM 782
#define NB_PREPW 256
#define NB_HIST 6250
#define SCAN_NB 782
#define NB_FU 1563                         // ceil(N_NODES/64)

// ---------------- scratch ----------------
__device__ float g_x[(size_t)N_NODES * H_DIM];
__device__ float g_h[(size_t)N_NODES * H_DIM];
__device__ int   g_cnt[SCAN_NB * 1024];     // zero-init; re-zeroed by scan each run
__device__ int   g_rowptr[NSEG + 1];
__device__ int   g_wp[NSEG];
__device__ unsigned long long g_flags[SCAN_NB];  // zero-init; re-zeroed by scatter
__device__ int2  g_emeta[N_EDGES];          // {src | (dst&7)<<20, norm-bits}
__device__ __align__(16) __nv_bfloat16 g_Wth[2 * H_DIM * K_TOT];   // [layer][o*512 + r*64+k]
__device__ __align__(16) __nv_bfloat16 g_Wtl[2 * H_DIM * K_TOT];

// ---------------- helpers ----------------
__device__ __forceinline__ void mma16816(float* c, const uint32_t* a, const uint32_t* b) {
    asm volatile(
        "mma.sync.aligned.m16n8k16.row.col.f32.bf16.bf16.f32 "
        "{%0,%1,%2,%3}, {%4,%5,%6,%7}, {%8,%9}, {%0,%1,%2,%3};\n"
        : "+f"(c[0]), "+f"(c[1]), "+f"(c[2]), "+f"(c[3])
        : "r"(a[0]), "r"(a[1]), "r"(a[2]), "r"(a[3]), "r"(b[0]), "r"(b[1]));
}

__device__ __forceinline__ void ldsm4(uint32_t* r, uint32_t addr) {
    asm volatile("ldmatrix.sync.aligned.m8n8.x4.shared.b16 {%0,%1,%2,%3}, [%4];"
        : "=r"(r[0]), "=r"(r[1]), "=r"(r[2]), "=r"(r[3]) : "r"(addr));
}

// predicated 128-bit smem store: fires only when cond != 0 (no BSSY/branch)
__device__ __forceinline__ void sts128_pred(uint32_t addr, float4 v, int cond) {
    asm volatile(
        "{\n\t.reg .pred p;\n\t"
        "setp.ne.s32 p, %5, 0;\n\t"
        "@p st.shared.v4.f32 [%0], {%1,%2,%3,%4};\n\t}"
        :: "r"(addr), "f"(v.x), "f"(v.y), "f"(v.z), "f"(v.w), "r"(cond) : "memory");
}

__device__ __forceinline__ void split_bf16(float v, __nv_bfloat16& hi, __nv_bfloat16& lo) {
    hi = __float2bfloat16(v);
    lo = __float2bfloat16(v - __bfloat162float(hi));
}

__device__ __forceinline__ uint32_t pack_bf2(__nv_bfloat16 a, __nv_bfloat16 b) {
    __nv_bfloat162 p; p.x = a; p.y = b;
    return *(uint32_t*)&p;
}

// split a float4 into packed hi/lo bf16x2 uint2s
__device__ __forceinline__ void split4(float4 v, uint2& hp, uint2& lp) {
    __nv_bfloat16 h0, l0, h1, l1, h2, l2, h3, l3;
    split_bf16(v.x, h0, l0); split_bf16(v.y, h1, l1);
    split_bf16(v.z, h2, l2); split_bf16(v.w, h3, l3);
    hp = make_uint2(pack_bf2(h0, h1), pack_bf2(h2, h3));
    lp = make_uint2(pack_bf2(l0, l1), pack_bf2(l2, l3));
}

// ---------------- size matcher body (256 threads/block), vectorized fills ----------
__device__ void sm_body(int bid, const int* __restrict__ feat, const float* __restrict__ emb,
                        const float* __restrict__ smw, const float* __restrict__ smb,
                        char* smraw) {
    __nv_bfloat16* Ahi = (__nv_bfloat16*)smraw;
    __nv_bfloat16* Alo = Ahi + 128 * NLDA;
    __nv_bfloat16* Bhi = Alo + 128 * NLDA;
    __nv_bfloat16* Blo = Bhi + 64 * NLDA;
    int* sfeat = (int*)(Blo + 64 * NLDA);

    int tid = threadIdx.x;
    int rb = bid * 128;

    for (int idx = tid; idx < 128 * 8; idx += 256) {
        int r = idx >> 3, j = idx & 7;
        sfeat[idx] = (rb + r < N_NODES) ? feat[(size_t)(rb + r) * 8 + j] : 0;
    }

    int lane = tid & 31, warp = tid >> 5;
    int wr = (warp >> 2) * 64;
    int wc = (warp & 3) * 16;
    int g = lane >> 2, t = lane & 3;

    float C[8][4];
    #pragma unroll
    for (int i = 0; i < 8; i++)
        #pragma unroll
        for (int j = 0; j < 4; j++) C[i][j] = 0.f;

    for (int kc = 0; kc < 4; kc++) {
        __syncthreads();
        // A chunk fill: float4 gather + packed hi/lo stores (8 iters/thread)
        for (int idx = tid; idx < 128 * 16; idx += 256) {
            int row = idx >> 4, q = idx & 15;
            float4 v = make_float4(0.f, 0.f, 0.f, 0.f);
            if (rb + row < N_NODES) {
                int fid = sfeat[row * 8 + kc * 2 + (q >> 3)];
                v = *(const float4*)(emb + (size_t)fid * 32 + (q & 7) * 4);
            }
            uint2 hp, lp; split4(v, hp, lp);
            *(uint2*)(Ahi + row * NLDA + q * 4) = hp;
            *(uint2*)(Alo + row * NLDA + q * 4) = lp;
        }
        // B chunk fill: float4 loads of smw (4 iters/thread)
        for (int idx = tid; idx < 64 * 16; idx += 256) {
            int n = idx >> 4, q = idx & 15;
            float4 v = *(const float4*)(smw + n * 256 + kc * 64 + q * 4);
            uint2 hp, lp; split4(v, hp, lp);
            *(uint2*)(Bhi + n * NLDA + q * 4) = hp;
            *(uint2*)(Blo + n * NLDA + q * 4) = lp;
        }
        __syncthreads();

        #pragma unroll
        for (int ks = 0; ks < 4; ks++) {
            int k0 = ks * 16;
            #pragma unroll
            for (int p = 0; p < 3; p++) {
                const __nv_bfloat16* As = (p == 1) ? Alo : Ahi;
                const __nv_bfloat16* Bs = (p == 2) ? Blo : Bhi;
                uint32_t a[4][4], b[2][2];
                #pragma unroll
                for (int mt = 0; mt < 4; mt++) {
                    int r0 = wr + mt * 16;
                    a[mt][0] = *(const uint32_t*)(As + (r0 + g) * NLDA + k0 + 2 * t);
                    a[mt][1] = *(const uint32_t*)(As + (r0 + g + 8) * NLDA + k0 + 2 * t);
                    a[mt][2] = *(const uint32_t*)(As + (r0 + g) * NLDA + k0 + 8 + 2 * t);
                    a[mt][3] = *(const uint32_t*)(As + (r0 + g + 8) * NLDA + k0 + 8 + 2 * t);
                }
                #pragma unroll
                for (int nt = 0; nt < 2; nt++) {
                    int c0 = wc + nt * 8 + g;
                    b[nt][0] = *(const uint32_t*)(Bs + c0 * NLDA + k0 + 2 * t);
                    b[nt][1] = *(const uint32_t*)(Bs + c0 * NLDA + k0 + 8 + 2 * t);
                }
                #pragma unroll
                for (int mt = 0; mt < 4; mt++)
                    #pragma unroll
                    for (int nt = 0; nt < 2; nt++)
                        mma16816(C[mt * 2 + nt], a[mt], b[nt]);
            }
        }
    }

    #pragma unroll
    for (int mt = 0; mt < 4; mt++) {
        int r0 = rb + wr + mt * 16 + g;
        int r1 = r0 + 8;
        #pragma unroll
        for (int nt = 0; nt < 2; nt++) {
            int gc = wc + nt * 8 + 2 * t;
            float b0 = smb[gc], b1 = smb[gc + 1];
            if (r0 < N_NODES)
                *(float2*)(g_x + (size_t)r0 * 64 + gc) =
                    make_float2(C[mt * 2 + nt][0] + b0, C[mt * 2 + nt][1] + b1);
            if (r1 < N_NODES)
                *(float2*)(g_x + (size_t)r1 * 64 + gc) =
                    make_float2(C[mt * 2 + nt][2] + b0, C[mt * 2 + nt][3] + b1);
        }
    }
}

// ---------------- front kernel: sm + prepw + hist ----------------
__global__ void k_front(const int* __restrict__ feat, const float* __restrict__ emb,
                        const float* __restrict__ smw, const float* __restrict__ smb,
                        const float* __restrict__ V1, const float* __restrict__ c1,
                        const float* __restrict__ V2, const float* __restrict__ c2,
                        const int* __restrict__ dst, const int* __restrict__ etype) {
    extern __shared__ char smraw[];
    int bid = blockIdx.x;
    if (bid < NB_SM) {
        sm_body(bid, feat, emb, smw, smb, smraw);
    } else if (bid < NB_SM + NB_PREPW) {
        int t = (bid - NB_SM) * 256 + threadIdx.x;
        int sel = t >= H_DIM * K_TOT;
        int u = t & (H_DIM * K_TOT - 1);
        int o = u >> 9;
        int c = u & 511;
        int r = c >> 6, k = c & 63;
        const float* V = sel ? V2 : V1;
        const float* cp = sel ? c2 : c1;
        float s = 0.f;
        #pragma unroll
        for (int b = 0; b < 8; b++)
            s += cp[r * 8 + b] * V[(b * 64 + k) * 64 + o];
        __nv_bfloat16 hi = __float2bfloat16(s);
        __nv_bfloat16 lo = __float2bfloat16(s - __bfloat162float(hi));
        g_Wth[t] = hi;
        g_Wtl[t] = lo;
    } else {
        int e = (bid - NB_SM - NB_PREPW) * 256 + threadIdx.x;
        if (e < N_EDGES)
            atomicAdd(&g_cnt[etype[e] * N_NODES + dst[e]], 1);
    }
}

// ---------------- single-kernel scan (decoupled lookback) ----------------
__global__ __launch_bounds__(1024) void k_scan() {
    __shared__ int wsum[32];
    __shared__ int s_excl;
    int tid = threadIdx.x, b = blockIdx.x;
    int i = b * 1024 + tid;
    int v = (i < NSEG) ? g_cnt[i] : 0;
    int lane = tid & 31, wid = tid >> 5;
    int s = v;
    #pragma unroll
    for (int d = 1; d < 32; d <<= 1) {
        int t = __shfl_up_sync(0xFFFFFFFFu, s, d);
        if (lane >= d) s += t;
    }
    if (lane == 31) wsum[wid] = s;
    __syncthreads();
    if (wid == 0) {
        int ws = wsum[lane];
        #pragma unroll
        for (int d = 1; d < 32; d <<= 1) {
            int t = __shfl_up_sync(0xFFFFFFFFu, ws, d);
            if (lane >= d) ws += t;
        }
        wsum[lane] = ws;
    }
    __syncthreads();
    int incl = s + ((wid > 0) ? wsum[wid - 1] : 0);
    int total = wsum[31];

    if (tid == 0) {
        unsigned long long f =
            ((unsigned long long)((b == 0) ? 2u : 1u) << 32) | (unsigned)total;
        atomicExch(&g_flags[b], f);
        if (b == 0) s_excl = 0;
    }
    if (b > 0 && wid == 0) {
        int running = 0;
        int p = b - 1;
        while (true) {
            int idx = p - lane;
            unsigned long long f = (idx >= 0) ? atomicOr(&g_flags[idx], 0ULL)
                                              : (2ULL << 32);
            unsigned st = (unsigned)(f >> 32);
            if (__ballot_sync(0xFFFFFFFFu, st == 0)) continue;
            unsigned b2 = __ballot_sync(0xFFFFFFFFu, st == 2);
            int val = (int)(unsigned)f;
            if (b2) {
                int k = __ffs(b2) - 1;
                int contrib = (lane <= k) ? val : 0;
                #pragma unroll
                for (int off = 16; off > 0; off >>= 1)
                    contrib += __shfl_xor_sync(0xFFFFFFFFu, contrib, off);
                running += contrib;
                break;
            } else {
                int contrib = val;
                #pragma unroll
                for (int off = 16; off > 0; off >>= 1)
                    contrib += __shfl_xor_sync(0xFFFFFFFFu, contrib, off);
                running += contrib;
                p -= 32;
            }
        }
        if (lane == 0) {
            s_excl = running;
            unsigned long long f = (2ULL << 32) | (unsigned)(running + total);
            atomicExch(&g_flags[b], f);
        }
    }
    __syncthreads();
    int rp = s_excl + incl - v;
    if (i < NSEG) {
        g_rowptr[i] = rp;
        g_wp[i] = rp;
        g_cnt[i] = 0;
    }
    if (i == NSEG - 1) g_rowptr[NSEG] = rp + v;
}

// ---------------- scatter (packs row = dst&7; re-zeroes g_flags) ----------------
__global__ void k_scatter(const int* __restrict__ src, const int* __restrict__ dst,
                          const int* __restrict__ etype, const float* __restrict__ norm) {
    int gid = blockIdx.x * blockDim.x + threadIdx.x;
    if (gid < SCAN_NB) g_flags[gid] = 0ULL;
    if (gid >= N_EDGES) return;
    int d = dst[gid];
    int seg = etype[gid] * N_NODES + d;
    int p = atomicAdd(&g_wp[seg], 1);
    g_emeta[p] = make_int2(src[gid] | ((d & 7) << 20), __float_as_int(norm[gid]));
}

// ---------------- fused layer v8: row×colgroup convert + v7 edge loop --------------
__global__ __launch_bounds__(256, 3)
void k_fused(int phase, const float* __restrict__ bias, float* __restrict__ dout) {
    const float* __restrict__ X = phase ? g_h : g_x;
    float* __restrict__ OP = phase ? dout : g_h;
    const __nv_bfloat16* __restrict__ Wh = g_Wth + phase * H_DIM * K_TOT;
    const __nv_bfloat16* __restrict__ Wl = g_Wtl + phase * H_DIM * K_TOT;

    extern __shared__ char smraw[];
    __nv_bfloat16* Ahi = (__nv_bfloat16*)smraw;         // 64*72  (9216 B)
    __nv_bfloat16* Alo = Ahi + 64 * NLDA;               // 9216 B
    __nv_bfloat16* Bhi = Alo + 64 * NLDA;               // 9216 B
    __nv_bfloat16* Blo = Bhi + 64 * NLDA;               // 9216 B
    float* Aacc = (float*)(Blo + 64 * NLDA);            // 128 rows * 68 fp32 (34816 B)

    int tid = threadIdx.x;
    int rb = blockIdx.x * 64;
    int lane = tid & 31, warp = tid >> 5;       // 8 warps
    int half = lane >> 4;
    int col4 = (lane & 15) * 4;

    int wr = (warp >> 2) * 32;                  // 0 or 32
    int wc = (warp & 3) * 16;                   // 0,16,32,48
    int g = lane >> 2, t = lane & 3;

    // ---- hoist all segment bounds: lane<16 -> relation lane>>1, bound lane&1 ----
    int bb = 0;
    {
        int nidx = min(rb + warp * 8 + ((lane & 1) << 3), N_NODES);
        if (lane < 16) bb = g_rowptr[(lane >> 1) * N_NODES + nidx];
    }

    // ldmatrix per-lane addresses (mapping validated in R7)
    int rowA = (lane & 7) + ((lane >> 3) & 1) * 8;
    int colA = ((lane >> 4) & 1) * 8;
    int rowB = (lane & 7) + ((lane >> 4) & 1) * 8;
    int colB = ((lane >> 3) & 1) * 8;
    uint32_t aHiAddr = (uint32_t)__cvta_generic_to_shared(Ahi) + (wr + rowA) * (NLDA * 2) + colA * 2;
    uint32_t aLoAddr = (uint32_t)__cvta_generic_to_shared(Alo) + (wr + rowA) * (NLDA * 2) + colA * 2;
    uint32_t bHiAddr = (uint32_t)__cvta_generic_to_shared(Bhi) + (wc + rowB) * (NLDA * 2) + colB * 2;
    uint32_t bLoAddr = (uint32_t)__cvta_generic_to_shared(Blo) + (wc + rowB) * (NLDA * 2) + colB * 2;

    float* AaccW = Aacc + (warp * 16) * ALDA;       // 16-row slab: bank0 rows 0-7, bank1 rows 8-15
    float* abase = AaccW + (half * 8) * ALDA + col4;
    uint32_t abaseAddr = (uint32_t)__cvta_generic_to_shared(abase);

    float C[4][4];
    #pragma unroll
    for (int i = 0; i < 4; i++)
        #pragma unroll
        for (int j = 0; j < 4; j++) C[i][j] = 0.f;

    for (int r = 0; r < NUM_RELS; r++) {
        // ===== zero own bank rows =====
        #pragma unroll
        for (int i = 0; i < 8; i++)
            *(float4*)(abase + i * ALDA) = make_float4(0.f, 0.f, 0.f, 0.f);

        // ===== warp edge range from hoisted registers (no LDG) =====
        int wbeg = __shfl_sync(0xFFFFFFFFu, bb, 2 * r);
        int wend = __shfl_sync(0xFFFFFFFFu, bb, 2 * r + 1);
        int cnt = wend - wbeg;

        // ===== aggregation: run-flush with software-pipelined meta =====
        {
            float4 acc = make_float4(0.f, 0.f, 0.f, 0.f);
            int cur = 0;
            int jmax = (cnt + 1) >> 1;         // edges for this half
            int eBase = wbeg + half;
            int eSafe = max(wend - 1, 0);
            int2 m0 = g_emeta[min(eBase, eSafe)];
            int2 m1 = g_emeta[min(eBase + 2, eSafe)];
            for (int j = 0; j < jmax; j += 2) {
                int e0 = eBase + 2 * j;
                int e1 = e0 + 2;
                int2 c0 = m0, c1 = m1;
                m0 = g_emeta[min(e1 + 2, eSafe)];      // prefetch next pair
                m1 = g_emeta[min(e1 + 4, eSafe)];
                float nn0 = (e0 < wend) ? __int_as_float(c0.y) : 0.f;
                float nn1 = (e1 < wend) ? __int_as_float(c1.y) : 0.f;
                float4 v0 = *(const float4*)(X + (size_t)(c0.x & 0xFFFFF) * 64 + col4);
                float4 v1 = *(const float4*)(X + (size_t)(c1.x & 0xFFFFF) * 64 + col4);
                int rw0 = (c0.x >> 20) & 7;
                int rw1 = (c1.x >> 20) & 7;

                int fl0 = rw0 - cur;                   // >0 on row change (sorted)
                sts128_pred(abaseAddr + cur * (ALDA * 4), acc, fl0);
                acc.x = fl0 ? 0.f : acc.x; acc.y = fl0 ? 0.f : acc.y;
                acc.z = fl0 ? 0.f : acc.z; acc.w = fl0 ? 0.f : acc.w;
                cur = rw0;
                acc.x = fmaf(nn0, v0.x, acc.x); acc.y = fmaf(nn0, v0.y, acc.y);
                acc.z = fmaf(nn0, v0.z, acc.z); acc.w = fmaf(nn0, v0.w, acc.w);

                int fl1 = rw1 - cur;
                sts128_pred(abaseAddr + cur * (ALDA * 4), acc, fl1);
                acc.x = fl1 ? 0.f : acc.x; acc.y = fl1 ? 0.f : acc.y;
                acc.z = fl1 ? 0.f : acc.z; acc.w = fl1 ? 0.f : acc.w;
                cur = rw1;
                acc.x = fmaf(nn1, v1.x, acc.x); acc.y = fmaf(nn1, v1.y, acc.y);
                acc.z = fmaf(nn1, v1.z, acc.z); acc.w = fmaf(nn1, v1.w, acc.w);
            }
            // final flush (cnt==0 -> stores zeros over pre-zeroed row 0: harmless)
            *(float4*)(abase + cur * ALDA) = acc;
        }

        __syncthreads();   // prior chunk's fragment reads + this chunk's Aacc ready

        // ===== convert v2: lane = (row l&7, colgroup l>>3); 8 LDS.128 + 4 STS.128 ====
        {
            int crow = lane & 7;
            int ccg = lane >> 3;                        // 0..3, 16 cols each
            const float* pa0 = AaccW + crow * ALDA + ccg * 16;
            const float* pa1 = pa0 + 8 * ALDA;
            uint32_t hb[8], lb[8];
            #pragma unroll
            for (int q = 0; q < 4; q++) {
                float4 u = *(const float4*)(pa0 + q * 4);
                float4 w = *(const float4*)(pa1 + q * 4);
                float f0 = u.x + w.x, f1 = u.y + w.y;
                float f2 = u.z + w.z, f3 = u.w + w.w;
                __nv_bfloat16 h0, l0, h1, l1, h2, l2, h3, l3;
                split_bf16(f0, h0, l0); split_bf16(f1, h1, l1);
                split_bf16(f2, h2, l2); split_bf16(f3, h3, l3);
                hb[q * 2]     = pack_bf2(h0, h1);
                hb[q * 2 + 1] = pack_bf2(h2, h3);
                lb[q * 2]     = pack_bf2(l0, l1);
                lb[q * 2 + 1] = pack_bf2(l2, l3);
            }
            int trow = warp * 8 + crow;
            uint4* dh = (uint4*)(Ahi + trow * NLDA + ccg * 16);
            uint4* dl = (uint4*)(Alo + trow * NLDA + ccg * 16);
            dh[0] = make_uint4(hb[0], hb[1], hb[2], hb[3]);
            dh[1] = make_uint4(hb[4], hb[5], hb[6], hb[7]);
            dl[0] = make_uint4(lb[0], lb[1], lb[2], lb[3]);
            dl[1] = make_uint4(lb[4], lb[5], lb[6], lb[7]);
        }

        // ===== B chunk copy, vectorized (2 uint4 per thread per array) =====
        for (int idx = tid; idx < 512; idx += 256) {
            int n = idx >> 3;
            int k8 = (idx & 7) * 8;
            *(uint4*)(Bhi + n * NLDA + k8) = *(const uint4*)(Wh + n * K_TOT + r * 64 + k8);
            *(uint4*)(Blo + n * NLDA + k8) = *(const uint4*)(Wl + n * K_TOT + r * 64 + k8);
        }
        __syncthreads();   // tiles ready

        // ===== 3-pass MMA via ldmatrix =====
        #pragma unroll
        for (int ks = 0; ks < 4; ks++) {
            uint32_t kb = ks * 32;
            uint32_t aH0[4], aH1[4], aL0[4], aL1[4], bH[4], bL[4];
            ldsm4(aH0, aHiAddr + kb);
            ldsm4(aH1, aHiAddr + 16 * (NLDA * 2) + kb);
            ldsm4(aL0, aLoAddr + kb);
            ldsm4(aL1, aLoAddr + 16 * (NLDA * 2) + kb);
            ldsm4(bH, bHiAddr + kb);
            ldsm4(bL, bLoAddr + kb);
            mma16816(C[0], aH0, bH + 0); mma16816(C[1], aH0, bH + 2);
            mma16816(C[2], aH1, bH + 0); mma16816(C[3], aH1, bH + 2);
            mma16816(C[0], aL0, bH + 0); mma16816(C[1], aL0, bH + 2);
            mma16816(C[2], aL1, bH + 0); mma16816(C[3], aL1, bH + 2);
            mma16816(C[0], aH0, bL + 0); mma16816(C[1], aH0, bL + 2);
            mma16816(C[2], aH1, bL + 0); mma16816(C[3], aH1, bL + 2);
        }
    }

    // ===== epilogue =====
    int dorelu = (phase == 0);
    #pragma unroll
    for (int mt = 0; mt < 2; mt++) {
        int r0 = rb + wr + mt * 16 + g;
        int r1 = r0 + 8;
        #pragma unroll
        for (int nt = 0; nt < 2; nt++) {
            int gc = wc + nt * 8 + 2 * t;
            float b0 = bias[gc], b1 = bias[gc + 1];
            float c00 = C[mt * 2 + nt][0] + b0, c01 = C[mt * 2 + nt][1] + b1;
            float c10 = C[mt * 2 + nt][2] + b0, c11 = C[mt * 2 + nt][3] + b1;
            if (dorelu) {
                c00 = fmaxf(c00, 0.f); c01 = fmaxf(c01, 0.f);
                c10 = fmaxf(c10, 0.f); c11 = fmaxf(c11, 0.f);
            }
            if (r0 < N_NODES)
                *(float2*)(OP + (size_t)r0 * 64 + gc) = make_float2(c00, c01);
            if (r1 < N_NODES)
                *(float2*)(OP + (size_t)r1 * 64 + gc) = make_float2(c10, c11);
        }
    }
}

// ---------------- launch ----------------
extern "C" void kernel_launch(void* const* d_in, const int* in_sizes, int n_in,
                              void* d_out, int out_size) {
    const int* feat = (const int*)d_in[0];
    const int* src = (const int*)d_in[1];
    const int* dst = (const int*)d_in[2];
    const int* etype = (const int*)d_in[3];
    const float* norm = (const float*)d_in[4];
    const float* emb = (const float*)d_in[5];
    const float* smw = (const float*)d_in[6];
    const float* smb = (const float*)d_in[7];
    const float* V1 = (const float*)d_in[8];
    const float* c1 = (const float*)d_in[9];
    const float* b1 = (const float*)d_in[10];
    const float* V2 = (const float*)d_in[11];
    const float* c2 = (const float*)d_in[12];
    const float* b2 = (const float*)d_in[13];
    float* out = (float*)d_out;

    const int smemSM = (128 * NLDA * 2 + 64 * NLDA * 2) * 2 + 128 * 8 * 4;
    const int smemFU = 64 * NLDA * 2 * 4 + 128 * ALDA * 4;   // 36864 + 34816 = 71680
    static int attr_done = 0;
    if (!attr_done) {
        cudaFuncSetAttribute(k_front, cudaFuncAttributeMaxDynamicSharedMemorySize, smemSM);
        cudaFuncSetAttribute(k_fused, cudaFuncAttributeMaxDynamicSharedMemorySize, smemFU);
        attr_done = 1;
    }

    k_front<<<NB_SM + NB_PREPW + NB_HIST, 256, smemSM>>>(feat, emb, smw, smb,
                                                         V1, c1, V2, c2, dst, etype);
    k_scan<<<SCAN_NB, 1024>>>();
    k_scatter<<<NB_HIST, 256>>>(src, dst, etype, norm);
    k_fused<<<NB_FU, 256, smemFU>>>(0, b1, nullptr);      // ncu capture slot
    k_fused<<<NB_FU, 256, smemFU>>>(1, b2, out);
}

// round 14
// speedup vs baseline: 2.5789x; 1.0403x over previous
#include <cuda_runtime.h>
#include <cuda_bf16.h>
#include <stdint.h>

#define N_NODES 100000
#define N_EDGES 1600000
#define NUM_RELS 8
#define H_DIM 64
#define K_TOT 512
#define NSEG (N_NODES * NUM_RELS)          // 800000
#define NLDA 72                            // bf16 elems; 144B row stride (16B aligned)
#define ALDA 68                            // Aacc fp32 leading dim (272B rows, conflict-free)
#define NB_SM 782
#define NB_PREPW 256
#define NB_HIST 6250
#define SCAN_NB 782
#define NB_FU 1563                         // ceil(N_NODES/64)

// ---------------- scratch ----------------
__device__ float g_x[(size_t)N_NODES * H_DIM];
__device__ float g_h[(size_t)N_NODES * H_DIM];
__device__ int   g_cnt[SCAN_NB * 1024];     // zero-init; re-zeroed by scan each run
__device__ int   g_rowptr[NSEG + 1];
__device__ int   g_wp[NSEG];
__device__ unsigned long long g_flags[SCAN_NB];  // zero-init; re-zeroed by scatter
__device__ int2  g_emeta[N_EDGES];          // {src | (dst&7)<<20, norm-bits}
__device__ __align__(16) __nv_bfloat16 g_Wth[2 * H_DIM * K_TOT];   // [layer][o*512 + r*64+k]
__device__ __align__(16) __nv_bfloat16 g_Wtl[2 * H_DIM * K_TOT];

// ---------------- helpers ----------------
__device__ __forceinline__ void mma16816(float* c, const uint32_t* a, const uint32_t* b) {
    asm volatile(
        "mma.sync.aligned.m16n8k16.row.col.f32.bf16.bf16.f32 "
        "{%0,%1,%2,%3}, {%4,%5,%6,%7}, {%8,%9}, {%0,%1,%2,%3};\n"
        : "+f"(c[0]), "+f"(c[1]), "+f"(c[2]), "+f"(c[3])
        : "r"(a[0]), "r"(a[1]), "r"(a[2]), "r"(a[3]), "r"(b[0]), "r"(b[1]));
}

__device__ __forceinline__ void ldsm4(uint32_t* r, uint32_t addr) {
    asm volatile("ldmatrix.sync.aligned.m8n8.x4.shared.b16 {%0,%1,%2,%3}, [%4];"
        : "=r"(r[0]), "=r"(r[1]), "=r"(r[2]), "=r"(r[3]) : "r"(addr));
}

// predicated 128-bit smem store: fires only when cond != 0 (no BSSY/branch)
__device__ __forceinline__ void sts128_pred(uint32_t addr, float4 v, int cond) {
    asm volatile(
        "{\n\t.reg .pred p;\n\t"
        "setp.ne.s32 p, %5, 0;\n\t"
        "@p st.shared.v4.f32 [%0], {%1,%2,%3,%4};\n\t}"
        :: "r"(addr), "f"(v.x), "f"(v.y), "f"(v.z), "f"(v.w), "r"(cond) : "memory");
}

__device__ __forceinline__ void split_bf16(float v, __nv_bfloat16& hi, __nv_bfloat16& lo) {
    hi = __float2bfloat16(v);
    lo = __float2bfloat16(v - __bfloat162float(hi));
}

__device__ __forceinline__ uint32_t pack_bf2(__nv_bfloat16 a, __nv_bfloat16 b) {
    __nv_bfloat162 p; p.x = a; p.y = b;
    return *(uint32_t*)&p;
}

// split a float4 into packed hi/lo bf16x2 uint2s
__device__ __forceinline__ void split4(float4 v, uint2& hp, uint2& lp) {
    __nv_bfloat16 h0, l0, h1, l1, h2, l2, h3, l3;
    split_bf16(v.x, h0, l0); split_bf16(v.y, h1, l1);
    split_bf16(v.z, h2, l2); split_bf16(v.w, h3, l3);
    hp = make_uint2(pack_bf2(h0, h1), pack_bf2(h2, h3));
    lp = make_uint2(pack_bf2(l0, l1), pack_bf2(l2, l3));
}

// ---------------- size matcher body (256 threads/block), vectorized fills ----------
__device__ void sm_body(int bid, const int* __restrict__ feat, const float* __restrict__ emb,
                        const float* __restrict__ smw, const float* __restrict__ smb,
                        char* smraw) {
    __nv_bfloat16* Ahi = (__nv_bfloat16*)smraw;
    __nv_bfloat16* Alo = Ahi + 128 * NLDA;
    __nv_bfloat16* Bhi = Alo + 128 * NLDA;
    __nv_bfloat16* Blo = Bhi + 64 * NLDA;
    int* sfeat = (int*)(Blo + 64 * NLDA);

    int tid = threadIdx.x;
    int rb = bid * 128;

    for (int idx = tid; idx < 128 * 8; idx += 256) {
        int r = idx >> 3, j = idx & 7;
        sfeat[idx] = (rb + r < N_NODES) ? feat[(size_t)(rb + r) * 8 + j] : 0;
    }

    int lane = tid & 31, warp = tid >> 5;
    int wr = (warp >> 2) * 64;
    int wc = (warp & 3) * 16;
    int g = lane >> 2, t = lane & 3;

    float C[8][4];
    #pragma unroll
    for (int i = 0; i < 8; i++)
        #pragma unroll
        for (int j = 0; j < 4; j++) C[i][j] = 0.f;

    for (int kc = 0; kc < 4; kc++) {
        __syncthreads();
        // A chunk fill: float4 gather + packed hi/lo stores (8 iters/thread)
        for (int idx = tid; idx < 128 * 16; idx += 256) {
            int row = idx >> 4, q = idx & 15;
            float4 v = make_float4(0.f, 0.f, 0.f, 0.f);
            if (rb + row < N_NODES) {
                int fid = sfeat[row * 8 + kc * 2 + (q >> 3)];
                v = *(const float4*)(emb + (size_t)fid * 32 + (q & 7) * 4);
            }
            uint2 hp, lp; split4(v, hp, lp);
            *(uint2*)(Ahi + row * NLDA + q * 4) = hp;
            *(uint2*)(Alo + row * NLDA + q * 4) = lp;
        }
        // B chunk fill: float4 loads of smw (4 iters/thread)
        for (int idx = tid; idx < 64 * 16; idx += 256) {
            int n = idx >> 4, q = idx & 15;
            float4 v = *(const float4*)(smw + n * 256 + kc * 64 + q * 4);
            uint2 hp, lp; split4(v, hp, lp);
            *(uint2*)(Bhi + n * NLDA + q * 4) = hp;
            *(uint2*)(Blo + n * NLDA + q * 4) = lp;
        }
        __syncthreads();

        #pragma unroll
        for (int ks = 0; ks < 4; ks++) {
            int k0 = ks * 16;
            #pragma unroll
            for (int p = 0; p < 3; p++) {
                const __nv_bfloat16* As = (p == 1) ? Alo : Ahi;
                const __nv_bfloat16* Bs = (p == 2) ? Blo : Bhi;
                uint32_t a[4][4], b[2][2];
                #pragma unroll
                for (int mt = 0; mt < 4; mt++) {
                    int r0 = wr + mt * 16;
                    a[mt][0] = *(const uint32_t*)(As + (r0 + g) * NLDA + k0 + 2 * t);
                    a[mt][1] = *(const uint32_t*)(As + (r0 + g + 8) * NLDA + k0 + 2 * t);
                    a[mt][2] = *(const uint32_t*)(As + (r0 + g) * NLDA + k0 + 8 + 2 * t);
                    a[mt][3] = *(const uint32_t*)(As + (r0 + g + 8) * NLDA + k0 + 8 + 2 * t);
                }
                #pragma unroll
                for (int nt = 0; nt < 2; nt++) {
                    int c0 = wc + nt * 8 + g;
                    b[nt][0] = *(const uint32_t*)(Bs + c0 * NLDA + k0 + 2 * t);
                    b[nt][1] = *(const uint32_t*)(Bs + c0 * NLDA + k0 + 8 + 2 * t);
                }
                #pragma unroll
                for (int mt = 0; mt < 4; mt++)
                    #pragma unroll
                    for (int nt = 0; nt < 2; nt++)
                        mma16816(C[mt * 2 + nt], a[mt], b[nt]);
            }
        }
    }

    #pragma unroll
    for (int mt = 0; mt < 4; mt++) {
        int r0 = rb + wr + mt * 16 + g;
        int r1 = r0 + 8;
        #pragma unroll
        for (int nt = 0; nt < 2; nt++) {
            int gc = wc + nt * 8 + 2 * t;
            float b0 = smb[gc], b1 = smb[gc + 1];
            if (r0 < N_NODES)
                *(float2*)(g_x + (size_t)r0 * 64 + gc) =
                    make_float2(C[mt * 2 + nt][0] + b0, C[mt * 2 + nt][1] + b1);
            if (r1 < N_NODES)
                *(float2*)(g_x + (size_t)r1 * 64 + gc) =
                    make_float2(C[mt * 2 + nt][2] + b0, C[mt * 2 + nt][3] + b1);
        }
    }
}

// ---------------- front kernel: sm + prepw + hist ----------------
__global__ void k_front(const int* __restrict__ feat, const float* __restrict__ emb,
                        const float* __restrict__ smw, const float* __restrict__ smb,
                        const float* __restrict__ V1, const float* __restrict__ c1,
                        const float* __restrict__ V2, const float* __restrict__ c2,
                        const int* __restrict__ dst, const int* __restrict__ etype) {
    extern __shared__ char smraw[];
    int bid = blockIdx.x;
    if (bid < NB_SM) {
        sm_body(bid, feat, emb, smw, smb, smraw);
    } else if (bid < NB_SM + NB_PREPW) {
        int t = (bid - NB_SM) * 256 + threadIdx.x;
        int sel = t >= H_DIM * K_TOT;
        int u = t & (H_DIM * K_TOT - 1);
        int o = u >> 9;
        int c = u & 511;
        int r = c >> 6, k = c & 63;
        const float* V = sel ? V2 : V1;
        const float* cp = sel ? c2 : c1;
        float s = 0.f;
        #pragma unroll
        for (int b = 0; b < 8; b++)
            s += cp[r * 8 + b] * V[(b * 64 + k) * 64 + o];
        __nv_bfloat16 hi = __float2bfloat16(s);
        __nv_bfloat16 lo = __float2bfloat16(s - __bfloat162float(hi));
        g_Wth[t] = hi;
        g_Wtl[t] = lo;
    } else {
        int e = (bid - NB_SM - NB_PREPW) * 256 + threadIdx.x;
        if (e < N_EDGES)
            atomicAdd(&g_cnt[etype[e] * N_NODES + dst[e]], 1);
    }
}

// ---------------- single-kernel scan (decoupled lookback) ----------------
__global__ __launch_bounds__(1024) void k_scan() {
    __shared__ int wsum[32];
    __shared__ int s_excl;
    int tid = threadIdx.x, b = blockIdx.x;
    int i = b * 1024 + tid;
    int v = (i < NSEG) ? g_cnt[i] : 0;
    int lane = tid & 31, wid = tid >> 5;
    int s = v;
    #pragma unroll
    for (int d = 1; d < 32; d <<= 1) {
        int t = __shfl_up_sync(0xFFFFFFFFu, s, d);
        if (lane >= d) s += t;
    }
    if (lane == 31) wsum[wid] = s;
    __syncthreads();
    if (wid == 0) {
        int ws = wsum[lane];
        #pragma unroll
        for (int d = 1; d < 32; d <<= 1) {
            int t = __shfl_up_sync(0xFFFFFFFFu, ws, d);
            if (lane >= d) ws += t;
        }
        wsum[lane] = ws;
    }
    __syncthreads();
    int incl = s + ((wid > 0) ? wsum[wid - 1] : 0);
    int total = wsum[31];

    if (tid == 0) {
        unsigned long long f =
            ((unsigned long long)((b == 0) ? 2u : 1u) << 32) | (unsigned)total;
        atomicExch(&g_flags[b], f);
        if (b == 0) s_excl = 0;
    }
    if (b > 0 && wid == 0) {
        int running = 0;
        int p = b - 1;
        while (true) {
            int idx = p - lane;
            unsigned long long f = (idx >= 0) ? atomicOr(&g_flags[idx], 0ULL)
                                              : (2ULL << 32);
            unsigned st = (unsigned)(f >> 32);
            if (__ballot_sync(0xFFFFFFFFu, st == 0)) continue;
            unsigned b2 = __ballot_sync(0xFFFFFFFFu, st == 2);
            int val = (int)(unsigned)f;
            if (b2) {
                int k = __ffs(b2) - 1;
                int contrib = (lane <= k) ? val : 0;
                #pragma unroll
                for (int off = 16; off > 0; off >>= 1)
                    contrib += __shfl_xor_sync(0xFFFFFFFFu, contrib, off);
                running += contrib;
                break;
            } else {
                int contrib = val;
                #pragma unroll
                for (int off = 16; off > 0; off >>= 1)
                    contrib += __shfl_xor_sync(0xFFFFFFFFu, contrib, off);
                running += contrib;
                p -= 32;
            }
        }
        if (lane == 0) {
            s_excl = running;
            unsigned long long f = (2ULL << 32) | (unsigned)(running + total);
            atomicExch(&g_flags[b], f);
        }
    }
    __syncthreads();
    int rp = s_excl + incl - v;
    if (i < NSEG) {
        g_rowptr[i] = rp;
        g_wp[i] = rp;
        g_cnt[i] = 0;
    }
    if (i == NSEG - 1) g_rowptr[NSEG] = rp + v;
}

// ---------------- scatter (packs row = dst&7; re-zeroes g_flags) ----------------
__global__ void k_scatter(const int* __restrict__ src, const int* __restrict__ dst,
                          const int* __restrict__ etype, const float* __restrict__ norm) {
    int gid = blockIdx.x * blockDim.x + threadIdx.x;
    if (gid < SCAN_NB) g_flags[gid] = 0ULL;
    if (gid >= N_EDGES) return;
    int d = dst[gid];
    int seg = etype[gid] * N_NODES + d;
    int p = atomicAdd(&g_wp[seg], 1);
    g_emeta[p] = make_int2(src[gid] | ((d & 7) << 20), __float_as_int(norm[gid]));
}

// ---------------- fused layer v9: no-zero Aacc via row-valid masks ----------------
__global__ __launch_bounds__(256, 3)
void k_fused(int phase, const float* __restrict__ bias, float* __restrict__ dout) {
    const float* __restrict__ X = phase ? g_h : g_x;
    float* __restrict__ OP = phase ? dout : g_h;
    const __nv_bfloat16* __restrict__ Wh = g_Wth + phase * H_DIM * K_TOT;
    const __nv_bfloat16* __restrict__ Wl = g_Wtl + phase * H_DIM * K_TOT;

    extern __shared__ char smraw[];
    __nv_bfloat16* Ahi = (__nv_bfloat16*)smraw;         // 64*72  (9216 B)
    __nv_bfloat16* Alo = Ahi + 64 * NLDA;               // 9216 B
    __nv_bfloat16* Bhi = Alo + 64 * NLDA;               // 9216 B
    __nv_bfloat16* Blo = Bhi + 64 * NLDA;               // 9216 B
    float* Aacc = (float*)(Blo + 64 * NLDA);            // 128 rows * 68 fp32 (34816 B)

    int tid = threadIdx.x;
    int rb = blockIdx.x * 64;
    int lane = tid & 31, warp = tid >> 5;       // 8 warps
    int half = lane >> 4;
    int col4 = (lane & 15) * 4;

    int wr = (warp >> 2) * 32;                  // 0 or 32
    int wc = (warp & 3) * 16;                   // 0,16,32,48
    int g = lane >> 2, t = lane & 3;

    // ---- hoist all segment bounds: lane<16 -> relation lane>>1, bound lane&1 ----
    int bb = 0;
    {
        int nidx = min(rb + warp * 8 + ((lane & 1) << 3), N_NODES);
        if (lane < 16) bb = g_rowptr[(lane >> 1) * N_NODES + nidx];
    }

    // ldmatrix per-lane addresses (mapping validated in R7)
    int rowA = (lane & 7) + ((lane >> 3) & 1) * 8;
    int colA = ((lane >> 4) & 1) * 8;
    int rowB = (lane & 7) + ((lane >> 4) & 1) * 8;
    int colB = ((lane >> 3) & 1) * 8;
    uint32_t aHiAddr = (uint32_t)__cvta_generic_to_shared(Ahi) + (wr + rowA) * (NLDA * 2) + colA * 2;
    uint32_t aLoAddr = (uint32_t)__cvta_generic_to_shared(Alo) + (wr + rowA) * (NLDA * 2) + colA * 2;
    uint32_t bHiAddr = (uint32_t)__cvta_generic_to_shared(Bhi) + (wc + rowB) * (NLDA * 2) + colB * 2;
    uint32_t bLoAddr = (uint32_t)__cvta_generic_to_shared(Blo) + (wc + rowB) * (NLDA * 2) + colB * 2;

    float* AaccW = Aacc + (warp * 16) * ALDA;       // 16-row slab: bank0 rows 0-7, bank1 rows 8-15
    float* abase = AaccW + (half * 8) * ALDA + col4;
    uint32_t abaseAddr = (uint32_t)__cvta_generic_to_shared(abase);

    float C[4][4];
    #pragma unroll
    for (int i = 0; i < 4; i++)
        #pragma unroll
        for (int j = 0; j < 4; j++) C[i][j] = 0.f;

    for (int r = 0; r < NUM_RELS; r++) {
        // ===== warp edge range from hoisted registers (no LDG) =====
        int wbeg = __shfl_sync(0xFFFFFFFFu, bb, 2 * r);
        int wend = __shfl_sync(0xFFFFFFFFu, bb, 2 * r + 1);
        int cnt = wend - wbeg;

        // ===== aggregation: run-flush, track written rows (no pre-zeroing) =====
        uint32_t vmask = 0;      // half-uniform: bit k = row k of this bank was stored
        {
            float4 acc = make_float4(0.f, 0.f, 0.f, 0.f);
            int cur = 0;
            int jmax = (cnt + 1) >> 1;         // edges for this half
            int eBase = wbeg + half;
            int eSafe = max(wend - 1, 0);
            int2 m0 = g_emeta[min(eBase, eSafe)];
            int2 m1 = g_emeta[min(eBase + 2, eSafe)];
            for (int j = 0; j < jmax; j += 2) {
                int e0 = eBase + 2 * j;
                int e1 = e0 + 2;
                int2 c0 = m0, c1 = m1;
                m0 = g_emeta[min(e1 + 2, eSafe)];      // prefetch next pair
                m1 = g_emeta[min(e1 + 4, eSafe)];
                float nn0 = (e0 < wend) ? __int_as_float(c0.y) : 0.f;
                float nn1 = (e1 < wend) ? __int_as_float(c1.y) : 0.f;
                float4 v0 = *(const float4*)(X + (size_t)(c0.x & 0xFFFFF) * 64 + col4);
                float4 v1 = *(const float4*)(X + (size_t)(c1.x & 0xFFFFF) * 64 + col4);
                int rw0 = (c0.x >> 20) & 7;
                int rw1 = (c1.x >> 20) & 7;

                int fl0 = rw0 - cur;                   // >0 on row change (sorted)
                sts128_pred(abaseAddr + cur * (ALDA * 4), acc, fl0);
                vmask |= (fl0 ? 1u : 0u) << cur;
                acc.x = fl0 ? 0.f : acc.x; acc.y = fl0 ? 0.f : acc.y;
                acc.z = fl0 ? 0.f : acc.z; acc.w = fl0 ? 0.f : acc.w;
                cur = rw0;
                acc.x = fmaf(nn0, v0.x, acc.x); acc.y = fmaf(nn0, v0.y, acc.y);
                acc.z = fmaf(nn0, v0.z, acc.z); acc.w = fmaf(nn0, v0.w, acc.w);

                int fl1 = rw1 - cur;
                sts128_pred(abaseAddr + cur * (ALDA * 4), acc, fl1);
                vmask |= (fl1 ? 1u : 0u) << cur;
                acc.x = fl1 ? 0.f : acc.x; acc.y = fl1 ? 0.f : acc.y;
                acc.z = fl1 ? 0.f : acc.z; acc.w = fl1 ? 0.f : acc.w;
                cur = rw1;
                acc.x = fmaf(nn1, v1.x, acc.x); acc.y = fmaf(nn1, v1.y, acc.y);
                acc.z = fmaf(nn1, v1.z, acc.z); acc.w = fmaf(nn1, v1.w, acc.w);
            }
            // final flush (cnt==0 -> stores zeros to row 0, marked valid: harmless)
            *(float4*)(abase + cur * ALDA) = acc;
            vmask |= 1u << cur;
        }

        __syncthreads();   // prior chunk's fragment reads + this chunk's Aacc ready

        // bank valid masks (half-uniform values, published via shfl)
        uint32_t mk0 = __shfl_sync(0xFFFFFFFFu, vmask, 0);
        uint32_t mk1 = __shfl_sync(0xFFFFFFFFu, vmask, 16);

        // ===== convert: masked bank sum -> bf16 hi/lo tiles =====
        {
            int crow = lane & 7;
            int ccg = lane >> 3;                        // 0..3, 16 cols each
            int b0 = (mk0 >> crow) & 1;
            int b1 = (mk1 >> crow) & 1;
            const float* pa0 = AaccW + crow * ALDA + ccg * 16;
            const float* pa1 = pa0 + 8 * ALDA;
            uint32_t hb[8], lb[8];
            #pragma unroll
            for (int q = 0; q < 4; q++) {
                float4 u = *(const float4*)(pa0 + q * 4);
                float4 w = *(const float4*)(pa1 + q * 4);
                float f0 = (b0 ? u.x : 0.f) + (b1 ? w.x : 0.f);
                float f1 = (b0 ? u.y : 0.f) + (b1 ? w.y : 0.f);
                float f2 = (b0 ? u.z : 0.f) + (b1 ? w.z : 0.f);
                float f3 = (b0 ? u.w : 0.f) + (b1 ? w.w : 0.f);
                __nv_bfloat16 h0, l0, h1, l1, h2, l2, h3, l3;
                split_bf16(f0, h0, l0); split_bf16(f1, h1, l1);
                split_bf16(f2, h2, l2); split_bf16(f3, h3, l3);
                hb[q * 2]     = pack_bf2(h0, h1);
                hb[q * 2 + 1] = pack_bf2(h2, h3);
                lb[q * 2]     = pack_bf2(l0, l1);
                lb[q * 2 + 1] = pack_bf2(l2, l3);
            }
            int trow = warp * 8 + crow;
            uint4* dh = (uint4*)(Ahi + trow * NLDA + ccg * 16);
            uint4* dl = (uint4*)(Alo + trow * NLDA + ccg * 16);
            dh[0] = make_uint4(hb[0], hb[1], hb[2], hb[3]);
            dh[1] = make_uint4(hb[4], hb[5], hb[6], hb[7]);
            dl[0] = make_uint4(lb[0], lb[1], lb[2], lb[3]);
            dl[1] = make_uint4(lb[4], lb[5], lb[6], lb[7]);
        }

        // ===== B chunk copy, vectorized (2 uint4 per thread per array) =====
        for (int idx = tid; idx < 512; idx += 256) {
            int n = idx >> 3;
            int k8 = (idx & 7) * 8;
            *(uint4*)(Bhi + n * NLDA + k8) = *(const uint4*)(Wh + n * K_TOT + r * 64 + k8);
            *(uint4*)(Blo + n * NLDA + k8) = *(const uint4*)(Wl + n * K_TOT + r * 64 + k8);
        }
        __syncthreads();   // tiles ready

        // ===== 3-pass MMA via ldmatrix =====
        #pragma unroll
        for (int ks = 0; ks < 4; ks++) {
            uint32_t kb = ks * 32;
            uint32_t aH0[4], aH1[4], aL0[4], aL1[4], bH[4], bL[4];
            ldsm4(aH0, aHiAddr + kb);
            ldsm4(aH1, aHiAddr + 16 * (NLDA * 2) + kb);
            ldsm4(aL0, aLoAddr + kb);
            ldsm4(aL1, aLoAddr + 16 * (NLDA * 2) + kb);
            ldsm4(bH, bHiAddr + kb);
            ldsm4(bL, bLoAddr + kb);
            mma16816(C[0], aH0, bH + 0); mma16816(C[1], aH0, bH + 2);
            mma16816(C[2], aH1, bH + 0); mma16816(C[3], aH1, bH + 2);
            mma16816(C[0], aL0, bH + 0); mma16816(C[1], aL0, bH + 2);
            mma16816(C[2], aL1, bH + 0); mma16816(C[3], aL1, bH + 2);
            mma16816(C[0], aH0, bL + 0); mma16816(C[1], aH0, bL + 2);
            mma16816(C[2], aH1, bL + 0); mma16816(C[3], aH1, bL + 2);
        }
    }

    // ===== epilogue =====
    int dorelu = (phase == 0);
    #pragma unroll
    for (int mt = 0; mt < 2; mt++) {
        int r0 = rb + wr + mt * 16 + g;
        int r1 = r0 + 8;
        #pragma unroll
        for (int nt = 0; nt < 2; nt++) {
            int gc = wc + nt * 8 + 2 * t;
            float b0 = bias[gc], b1 = bias[gc + 1];
            float c00 = C[mt * 2 + nt][0] + b0, c01 = C[mt * 2 + nt][1] + b1;
            float c10 = C[mt * 2 + nt][2] + b0, c11 = C[mt * 2 + nt][3] + b1;
            if (dorelu) {
                c00 = fmaxf(c00, 0.f); c01 = fmaxf(c01, 0.f);
                c10 = fmaxf(c10, 0.f); c11 = fmaxf(c11, 0.f);
            }
            if (r0 < N_NODES)
                *(float2*)(OP + (size_t)r0 * 64 + gc) = make_float2(c00, c01);
            if (r1 < N_NODES)
                *(float2*)(OP + (size_t)r1 * 64 + gc) = make_float2(c10, c11);
        }
    }
}

// ---------------- launch ----------------
extern "C" void kernel_launch(void* const* d_in, const int* in_sizes, int n_in,
                              void* d_out, int out_size) {
    const int* feat = (const int*)d_in[0];
    const int* src = (const int*)d_in[1];
    const int* dst = (const int*)d_in[2];
    const int* etype = (const int*)d_in[3];
    const float* norm = (const float*)d_in[4];
    const float* emb = (const float*)d_in[5];
    const float* smw = (const float*)d_in[6];
    const float* smb = (const float*)d_in[7];
    const float* V1 = (const float*)d_in[8];
    const float* c1 = (const float*)d_in[9];
    const float* b1 = (const float*)d_in[10];
    const float* V2 = (const float*)d_in[11];
    const float* c2 = (const float*)d_in[12];
    const float* b2 = (const float*)d_in[13];
    float* out = (float*)d_out;

    const int smemSM = (128 * NLDA * 2 + 64 * NLDA * 2) * 2 + 128 * 8 * 4;
    const int smemFU = 64 * NLDA * 2 * 4 + 128 * ALDA * 4;   // 36864 + 34816 = 71680
    static int attr_done = 0;
    if (!attr_done) {
        cudaFuncSetAttribute(k_front, cudaFuncAttributeMaxDynamicSharedMemorySize, smemSM);
        cudaFuncSetAttribute(k_fused, cudaFuncAttributeMaxDynamicSharedMemorySize, smemFU);
        attr_done = 1;
    }

    k_front<<<NB_SM + NB_PREPW + NB_HIST, 256, smemSM>>>(feat, emb, smw, smb,
                                                         V1, c1, V2, c2, dst, etype);
    k_scan<<<SCAN_NB, 1024>>>();
    k_scatter<<<NB_HIST, 256>>>(src, dst, etype, norm);
    k_fused<<<NB_FU, 256, smemFU>>>(0, b1, nullptr);      // ncu capture slot
    k_fused<<<NB_FU, 256, smemFU>>>(1, b2, out);
}